// round 14
// baseline (speedup 1.0000x reference)
#include <cuda_runtime.h>
#include <cuda_bf16.h>
#include <cstdint>

#define N_NODES 50000
#define N_EDGES 800000
#define DIMS 128
#define HEADS 4

// ---------------- scratch (__device__ globals: allocation-free) ----------------
__device__ int   g_cnt[2][N_NODES];
__device__ int   g_cur[2][N_NODES];
__device__ int   g_off[2][N_NODES + 1];
__device__ int   g_adj[2][N_EDGES];
__device__ float g_aggr[6ull * N_NODES * DIMS];            // planes: max0,min0,sum0,max1,min1,sum1
__device__ float g_m[(size_t)N_NODES * HEADS * DIMS];      // [node][h*128+j]
__device__ __nv_bfloat16 g_zh[(size_t)N_NODES * HEADS * DIMS];
__device__ __nv_bfloat16 g_zl[(size_t)N_NODES * HEADS * DIMS];
// folded weights (bf16 hi/lo split)
__device__ __nv_bfloat16 g_Bwh[512 * 128];  // [n][k]
__device__ __nv_bfloat16 g_Bwl[512 * 128];
__device__ __nv_bfloat16 g_Uh[128 * 512];   // [c][kk]
__device__ __nv_bfloat16 g_Ul[128 * 512];
__device__ float g_mconst[512];
__device__ float g_oconst[128];

// ---------------- warp MMA + async helpers (plain PTX, sm_80+) ----------------
__device__ __forceinline__ uint32_t smem_to_u32(const void* p) {
    uint32_t a;
    asm("{ .reg .u64 t; cvta.to.shared.u64 t, %1; cvt.u32.u64 %0, t; }" : "=r"(a) : "l"(p));
    return a;
}
__device__ __forceinline__ void ldsm4(uint32_t (&r)[4], uint32_t addr) {
    asm volatile("ldmatrix.sync.aligned.m8n8.x4.shared.b16 {%0,%1,%2,%3}, [%4];"
                 : "=r"(r[0]), "=r"(r[1]), "=r"(r[2]), "=r"(r[3]) : "r"(addr));
}
__device__ __forceinline__ void mma16816(float (&c)[4], const uint32_t (&a)[4],
                                         uint32_t b0, uint32_t b1) {
    asm volatile("mma.sync.aligned.m16n8k16.row.col.f32.bf16.bf16.f32 "
                 "{%0,%1,%2,%3}, {%4,%5,%6,%7}, {%8,%9}, {%0,%1,%2,%3};"
                 : "+f"(c[0]), "+f"(c[1]), "+f"(c[2]), "+f"(c[3])
                 : "r"(a[0]), "r"(a[1]), "r"(a[2]), "r"(a[3]), "r"(b0), "r"(b1));
}
__device__ __forceinline__ uint32_t pack_bf16(__nv_bfloat16 a, __nv_bfloat16 b) {
    __nv_bfloat162 t = __halves2bfloat162(a, b);
    return *(uint32_t*)&t;
}
__device__ __forceinline__ void cp16(uint32_t smem_addr, const void* gptr, uint32_t srcsize) {
    asm volatile("cp.async.cg.shared.global [%0], [%1], 16, %2;"
                 :: "r"(smem_addr), "l"(gptr), "r"(srcsize) : "memory");
}
#define CP_COMMIT() asm volatile("cp.async.commit_group;" ::: "memory")
#define CP_WAIT(n)  asm volatile("cp.async.wait_group %0;" :: "n"(n) : "memory")

// SMEM tile geometry: [128 rows][64 k] bf16, row stride 72 (144B, ldmatrix conflict-free)
#define TSTRIDE 72
#define TBYTES  (128 * TSTRIDE * 2)   // 18432
#define GEMM_SMEM (6 * TBYTES)        // 110592 -> 2 CTAs/SM

// ---------------- CSR build (per edge set) ----------------
__global__ void zero_kernel(int set) {
    int t = blockIdx.x * blockDim.x + threadIdx.x;
    if (t < N_NODES) {
        g_cnt[set][t] = 0;
        g_cur[set][t] = 0;
    }
}
__global__ void hist_kernel(const int* __restrict__ ei, int set) {
    int e = blockIdx.x * blockDim.x + threadIdx.x;
    if (e >= N_EDGES) return;
    atomicAdd(&g_cnt[set][ei[N_EDGES + e]], 1);
}
__global__ void scan_kernel(int set) {
    __shared__ int swarp[32];
    const int tid = threadIdx.x, lane = tid & 31, wid = tid >> 5;
    int carry = 0;
    if (tid == 0) g_off[set][0] = 0;
    for (int base = 0; base < N_NODES; base += 1024) {
        int i = base + tid;
        int v = (i < N_NODES) ? g_cnt[set][i] : 0;
        int incl = v;
        #pragma unroll
        for (int o = 1; o < 32; o <<= 1) {
            int t = __shfl_up_sync(0xffffffffu, incl, o);
            if (lane >= o) incl += t;
        }
        if (lane == 31) swarp[wid] = incl;
        __syncthreads();
        if (wid == 0) {
            int t = swarp[lane];
            #pragma unroll
            for (int o = 1; o < 32; o <<= 1) {
                int u = __shfl_up_sync(0xffffffffu, t, o);
                if (lane >= o) t += u;
            }
            swarp[lane] = t;
        }
        __syncthreads();
        int add = (wid > 0) ? swarp[wid - 1] : 0;
        if (i < N_NODES) g_off[set][i + 1] = carry + add + incl;
        carry += swarp[31];
        __syncthreads();
    }
}
__global__ void fill_kernel(const int* __restrict__ ei, int set) {
    int e = blockIdx.x * blockDim.x + threadIdx.x;
    if (e >= N_EDGES) return;
    int s = ei[e], d = ei[N_EDGES + e];
    int p = atomicAdd(&g_cur[set][d], 1);
    g_adj[set][g_off[set][d] + p] = s;
}

// ---------------- warp-per-node gather + max/min/sum (per set, 4-wide MLP) ----------------
__device__ __forceinline__ void acc3(float4& vmax, float4& vmin, float4& vsum, const float4 v) {
    vmax.x = fmaxf(vmax.x, v.x); vmax.y = fmaxf(vmax.y, v.y);
    vmax.z = fmaxf(vmax.z, v.z); vmax.w = fmaxf(vmax.w, v.w);
    vmin.x = fminf(vmin.x, v.x); vmin.y = fminf(vmin.y, v.y);
    vmin.z = fminf(vmin.z, v.z); vmin.w = fminf(vmin.w, v.w);
    vsum.x += v.x; vsum.y += v.y; vsum.z += v.z; vsum.w += v.w;
}
__global__ void agg_kernel(const float* __restrict__ x, int set) {
    int gw = (blockIdx.x * blockDim.x + threadIdx.x) >> 5;
    if (gw >= N_NODES) return;
    const int lane = threadIdx.x & 31;
    const int node = gw;
    const int beg = g_off[set][node], end = g_off[set][node + 1];
    const int* __restrict__ adj = g_adj[set];
    const size_t lo = (size_t)lane * 4;

    float4 vmax = make_float4(-3.402823466e38f, -3.402823466e38f, -3.402823466e38f, -3.402823466e38f);
    float4 vmin = make_float4( 3.402823466e38f,  3.402823466e38f,  3.402823466e38f,  3.402823466e38f);
    float4 vsum = make_float4(0.f, 0.f, 0.f, 0.f);

    int i = beg;
    for (; i + 4 <= end; i += 4) {
        int s0 = __ldg(adj + i + 0), s1 = __ldg(adj + i + 1);
        int s2 = __ldg(adj + i + 2), s3 = __ldg(adj + i + 3);
        float4 v0 = *(const float4*)(x + (size_t)s0 * DIMS + lo);
        float4 v1 = *(const float4*)(x + (size_t)s1 * DIMS + lo);
        float4 v2 = *(const float4*)(x + (size_t)s2 * DIMS + lo);
        float4 v3 = *(const float4*)(x + (size_t)s3 * DIMS + lo);
        acc3(vmax, vmin, vsum, v0);
        acc3(vmax, vmin, vsum, v1);
        acc3(vmax, vmin, vsum, v2);
        acc3(vmax, vmin, vsum, v3);
    }
    for (; i < end; i++) {
        int s = __ldg(adj + i);
        float4 v = *(const float4*)(x + (size_t)s * DIMS + lo);
        acc3(vmax, vmin, vsum, v);
    }

    const size_t plane = (size_t)N_NODES * DIMS;
    size_t base = ((size_t)(set * 3) * N_NODES + node) * DIMS + lo;
    if (end > beg) {
        *(float4*)(g_aggr + base)             = vmax;
        *(float4*)(g_aggr + base + plane)     = vmin;
        *(float4*)(g_aggr + base + 2 * plane) = vsum;
    } else {
        float4 z = make_float4(0.f, 0.f, 0.f, 0.f);
        *(float4*)(g_aggr + base)             = z;
        *(float4*)(g_aggr + base + plane)     = z;
        *(float4*)(g_aggr + base + 2 * plane) = z;
    }
}

// ---------------- fold weights: Bw, U, m_const, out_const ----------------
__global__ void precompute_kernel(const float* __restrict__ w_in,
                                  const float* __restrict__ b_in,
                                  const float* __restrict__ w_out,
                                  const float* __restrict__ b_out) {
    int t = blockIdx.x * blockDim.x + threadIdx.x;
    if (t < 512 * 128) {                    // Bw[n][k]
        int n = t >> 7, k = t & 127;
        int h = n >> 7, j = n & 127;
        float s = 0.f;
        #pragma unroll 8
        for (int i = 0; i < 32; i++)
            s += w_in[(size_t)(h * 32 + i) * 128 + k] * w_in[(size_t)(128 + h * 32 + i) * 128 + j];
        __nv_bfloat16 hi = __float2bfloat16(s);
        g_Bwh[t] = hi;
        g_Bwl[t] = __float2bfloat16(s - __bfloat162float(hi));
    } else if (t < 2 * 512 * 128) {         // U[c][kk]
        int u = t - 512 * 128;
        int c = u >> 9, kk = u & 511;
        int h = kk >> 7, d = kk & 127;
        float s = 0.f;
        #pragma unroll 8
        for (int i = 0; i < 32; i++)
            s += w_out[(size_t)c * 128 + h * 32 + i] * w_in[(size_t)(256 + h * 32 + i) * 128 + d];
        __nv_bfloat16 hi = __float2bfloat16(s);
        g_Uh[u] = hi;
        g_Ul[u] = __float2bfloat16(s - __bfloat162float(hi));
    } else if (t < 2 * 512 * 128 + 512) {   // m_const
        int n = t - 2 * 512 * 128;
        int h = n >> 7, j = n & 127;
        float s = 0.f;
        for (int i = 0; i < 32; i++)
            s += b_in[h * 32 + i] * w_in[(size_t)(128 + h * 32 + i) * 128 + j];
        g_mconst[n] = s;
    } else if (t < 2 * 512 * 128 + 512 + 128) {  // out_const
        int c = t - 2 * 512 * 128 - 512;
        float s = b_out[c];
        for (int n = 0; n < 128; n++)
            s += w_out[(size_t)c * 128 + n] * b_in[256 + n];
        g_oconst[c] = s;
    }
}

// per-lane ldmatrix source offsets (bytes) within a [*, TSTRIDE] bf16 tile
__device__ __forceinline__ uint32_t laneA_off(int lane) {
    int row = (lane < 16) ? lane : (lane - 16);
    int col = (lane < 16) ? 0 : 8;
    return (uint32_t)(row * TSTRIDE + col) * 2;
}
__device__ __forceinline__ uint32_t laneB_off(int lane) {
    int g = lane >> 3, r = lane & 7;
    int row = (g == 0 || g == 1) ? r : (8 + r);
    int col = (g == 1 || g == 3) ? 8 : 0;
    return (uint32_t)(row * TSTRIDE + col) * 2;
}
__device__ __forceinline__ void store_split4(char* base_h, char* base_l, int r, int k4, float4 v) {
    __nv_bfloat16 h0 = __float2bfloat16(v.x), h1 = __float2bfloat16(v.y);
    __nv_bfloat16 h2 = __float2bfloat16(v.z), h3 = __float2bfloat16(v.w);
    __nv_bfloat16 l0 = __float2bfloat16(v.x - __bfloat162float(h0));
    __nv_bfloat16 l1 = __float2bfloat16(v.y - __bfloat162float(h1));
    __nv_bfloat16 l2 = __float2bfloat16(v.z - __bfloat162float(h2));
    __nv_bfloat16 l3 = __float2bfloat16(v.w - __bfloat162float(h3));
    uint2 ph = make_uint2(pack_bf16(h0, h1), pack_bf16(h2, h3));
    uint2 pl = make_uint2(pack_bf16(l0, l1), pack_bf16(l2, l3));
    uint32_t off = (uint32_t)(r * TSTRIDE + k4 * 4) * 2;
    *(uint2*)(base_h + off) = ph;
    *(uint2*)(base_l + off) = pl;
}

// warp-tile MMA on one (A,B) smem tile pair with 3-pass hi/lo
__device__ __forceinline__ void mma_tile(uint32_t sb, uint32_t offAH, uint32_t offAL,
                                         uint32_t offBH, uint32_t offBL,
                                         uint32_t lA, uint32_t lB,
                                         int warp_m, int warp_n, float (&acc)[4][4][4]) {
    #pragma unroll
    for (int pass = 0; pass < 3; pass++) {
        const uint32_t Abase = sb + ((pass == 2) ? offAL : offAH);
        const uint32_t Bbase = sb + ((pass == 1) ? offBL : offBH);
        #pragma unroll
        for (int ks = 0; ks < 4; ks++) {
            uint32_t a[4][4];
            #pragma unroll
            for (int mf = 0; mf < 4; mf++)
                ldsm4(a[mf], Abase + lA + (uint32_t)((warp_m * 64 + mf * 16) * TSTRIDE + ks * 16) * 2);
            uint32_t b[2][4];
            #pragma unroll
            for (int nf2 = 0; nf2 < 2; nf2++)
                ldsm4(b[nf2], Bbase + lB + (uint32_t)((warp_n * 32 + nf2 * 16) * TSTRIDE + ks * 16) * 2);
            #pragma unroll
            for (int mf = 0; mf < 4; mf++)
                #pragma unroll
                for (int nf = 0; nf < 4; nf++)
                    mma16816(acc[mf][nf], a[mf], b[nf >> 1][(nf & 1) * 2], b[nf >> 1][(nf & 1) * 2 + 1]);
        }
    }
}

// ---------------- GEMM1 (HMMA, 2 CTA/SM): m = x @ Bw^T + m_const ----------------
// SMEM: A resident 4 tiles (AH0,AL0,AH1,AL1), B single stage 2 tiles.
__global__ __launch_bounds__(256) void gemm1_tc(const float* __restrict__ x) {
    extern __shared__ char sm[];
    const int tid = threadIdx.x, wid = tid >> 5, lane = tid & 31;
    const int warp_m = wid >> 2, warp_n = wid & 3;
    const int row0 = blockIdx.x * 128;
    const uint32_t sb = smem_to_u32(sm);
    const uint32_t lA = laneA_off(lane), lB = laneB_off(lane);
    const uint32_t BBASE = 4 * TBYTES;

    for (int kc = 0; kc < 2; kc++) {
        char* ah = sm + (2 * kc) * TBYTES;
        char* al = sm + (2 * kc + 1) * TBYTES;
        for (int it = tid; it < 128 * 16; it += 256) {
            int r = it >> 4, q = it & 15;
            int node = row0 + r;
            float4 v = (node < N_NODES)
                ? *(const float4*)(x + (size_t)node * 128 + kc * 64 + q * 4)
                : make_float4(0.f, 0.f, 0.f, 0.f);
            store_split4(ah, al, r, q, v);
        }
    }

    auto issueB = [&](int s) {
        int nc = s >> 1, kc = s & 1;
        uint32_t stb = sb + BBASE;
        for (int it = tid; it < 1024; it += 256) {
            int r = it >> 3, q = it & 7;
            size_t src = (size_t)(nc * 128 + r) * 128 + kc * 64 + q * 8;
            uint32_t dst = (uint32_t)(r * TSTRIDE + q * 8) * 2;
            cp16(stb + dst, g_Bwh + src, 16);
            cp16(stb + TBYTES + dst, g_Bwl + src, 16);
        }
        CP_COMMIT();
    };

    float acc[4][4][4];
    for (int s = 0; s < 8; s++) {
        int nc = s >> 1, kc = s & 1;
        if (kc == 0) {
            #pragma unroll
            for (int i = 0; i < 4; i++)
                #pragma unroll
                for (int j = 0; j < 4; j++)
                    #pragma unroll
                    for (int q = 0; q < 4; q++) acc[i][j][q] = 0.f;
        }
        issueB(s);
        CP_WAIT(0);
        __syncthreads();

        uint32_t offAH = (uint32_t)(2 * kc) * TBYTES;
        uint32_t offAL = offAH + TBYTES;
        mma_tile(sb, offAH, offAL, BBASE, BBASE + TBYTES, lA, lB, warp_m, warp_n, acc);
        __syncthreads();

        if (kc == 1) {
            #pragma unroll
            for (int mf = 0; mf < 4; mf++) {
                int r_lo = row0 + warp_m * 64 + mf * 16 + (lane >> 2);
                #pragma unroll
                for (int half = 0; half < 2; half++) {
                    int node = r_lo + half * 8;
                    if (node >= N_NODES) continue;
                    #pragma unroll
                    for (int nf = 0; nf < 4; nf++) {
                        int col = nc * 128 + warp_n * 32 + nf * 8 + (lane & 3) * 2;
                        float2 o;
                        o.x = acc[mf][nf][half * 2 + 0] + g_mconst[col];
                        o.y = acc[mf][nf][half * 2 + 1] + g_mconst[col + 1];
                        *(float2*)(g_m + (size_t)node * 512 + col) = o;
                    }
                }
            }
        }
    }
}

// ---------------- scores + softmax + z (warp per node; z written as bf16 hi/lo) ----------------
__device__ __forceinline__ float dot4(const float4 a, const float4 b) {
    return a.x * b.x + a.y * b.y + a.z * b.z + a.w * b.w;
}
__device__ __forceinline__ void axpy4(float4& z, const float4 v, float s) {
    z.x += v.x * s; z.y += v.y * s; z.z += v.z * s; z.w += v.w * s;
}
__global__ void attn_kernel(const float* __restrict__ x) {
    int gw = (blockIdx.x * blockDim.x + threadIdx.x) >> 5;
    if (gw >= N_NODES) return;
    const int lane = threadIdx.x & 31;
    const int node = gw;
    const size_t rb = (size_t)node * DIMS + lane * 4;
    const size_t plane = (size_t)N_NODES * DIMS;

    float4 vx = *(const float4*)(x + rb);
    float4 av[6];
    #pragma unroll
    for (int p = 0; p < 6; p++) av[p] = *(const float4*)(g_aggr + p * plane + rb);
    float4 vm[4];
    const size_t mb = (size_t)node * (HEADS * DIMS) + lane * 4;
    #pragma unroll
    for (int h = 0; h < HEADS; h++) vm[h] = *(const float4*)(g_m + mb + h * DIMS);

    float dt[4][7];
    #pragma unroll
    for (int h = 0; h < 4; h++) {
        dt[h][0] = dot4(vm[h], vx);
        #pragma unroll
        for (int p = 0; p < 6; p++) dt[h][1 + p] = dot4(vm[h], av[p]);
    }
    #pragma unroll
    for (int h = 0; h < 4; h++)
        #pragma unroll
        for (int v = 0; v < 7; v++) {
            float t = dt[h][v];
            #pragma unroll
            for (int o = 16; o; o >>= 1) t += __shfl_xor_sync(0xffffffffu, t, o);
            dt[h][v] = t;
        }

    const int cnt0 = g_cnt[0][node], cnt1 = g_cnt[1][node];
    const float c0 = (float)cnt0, c1 = (float)cnt1;
    const float sc = 0.17677669529663687f;  // 1/sqrt(32)

    #pragma unroll
    for (int h = 0; h < 4; h++) {
        float s0 = dt[h][0] * sc;
        float mx = s0;
        float a0 = 0.f, b0 = 0.f, u0 = 0.f, n0 = 0.f;
        float a1 = 0.f, b1 = 0.f, u1 = 0.f, n1 = 0.f;
        if (cnt0) {
            a0 = dt[h][1] * sc; b0 = dt[h][2] * sc; u0 = dt[h][3] * sc; n0 = u0 / c0;
            mx = fmaxf(mx, fmaxf(fmaxf(a0, b0), fmaxf(u0, n0)));
        }
        if (cnt1) {
            a1 = dt[h][4] * sc; b1 = dt[h][5] * sc; u1 = dt[h][6] * sc; n1 = u1 / c1;
            mx = fmaxf(mx, fmaxf(fmaxf(a1, b1), fmaxf(u1, n1)));
        }
        float eself = __expf(s0 - mx);
        float den = eself;
        float wm0 = 0.f, wn0 = 0.f, ws0 = 0.f, wm1 = 0.f, wn1 = 0.f, ws1 = 0.f;
        if (cnt0) {
            float e1 = __expf(a0 - mx), e2 = __expf(b0 - mx);
            float e3 = __expf(u0 - mx), e4 = __expf(n0 - mx);
            den += e1 + e2 + e3 + e4;
            wm0 = e1; wn0 = e2; ws0 = e3 + e4 / c0;
        }
        if (cnt1) {
            float e1 = __expf(a1 - mx), e2 = __expf(b1 - mx);
            float e3 = __expf(u1 - mx), e4 = __expf(n1 - mx);
            den += e1 + e2 + e3 + e4;
            wm1 = e1; wn1 = e2; ws1 = e3 + e4 / c1;
        }
        float inv = 1.f / den;
        float4 z = make_float4(0.f, 0.f, 0.f, 0.f);
        axpy4(z, vx, eself * inv);
        if (cnt0) { axpy4(z, av[0], wm0 * inv); axpy4(z, av[1], wn0 * inv); axpy4(z, av[2], ws0 * inv); }
        if (cnt1) { axpy4(z, av[3], wm1 * inv); axpy4(z, av[4], wn1 * inv); axpy4(z, av[5], ws1 * inv); }

        __nv_bfloat16 h0 = __float2bfloat16(z.x), h1 = __float2bfloat16(z.y);
        __nv_bfloat16 h2 = __float2bfloat16(z.z), h3 = __float2bfloat16(z.w);
        __nv_bfloat16 l0 = __float2bfloat16(z.x - __bfloat162float(h0));
        __nv_bfloat16 l1 = __float2bfloat16(z.y - __bfloat162float(h1));
        __nv_bfloat16 l2 = __float2bfloat16(z.z - __bfloat162float(h2));
        __nv_bfloat16 l3 = __float2bfloat16(z.w - __bfloat162float(h3));
        *(uint2*)(g_zh + mb + h * DIMS) = make_uint2(pack_bf16(h0, h1), pack_bf16(h2, h3));
        *(uint2*)(g_zl + mb + h * DIMS) = make_uint2(pack_bf16(l0, l1), pack_bf16(l2, l3));
    }
}

// ---------------- GEMM2 (HMMA, 2 CTA/SM): out = LN(z @ U^T + out_const) ----------------
// SMEM: A 2 stages x 2 tiles (z hi/lo, cp.async double-buffered), B single stage 2 tiles.
__global__ __launch_bounds__(256) void gemm2_tc(const float* __restrict__ gamma,
                                                const float* __restrict__ beta,
                                                float* __restrict__ out) {
    extern __shared__ char sm[];
    const int tid = threadIdx.x, wid = tid >> 5, lane = tid & 31;
    const int warp_m = wid >> 2, warp_n = wid & 3;
    const int row0 = blockIdx.x * 128;
    const uint32_t sb = smem_to_u32(sm);
    const uint32_t lA = laneA_off(lane), lB = laneB_off(lane);
    const uint32_t BBASE = 4 * TBYTES;

    auto issueA = [&](int kc, int st) {
        uint32_t stb = sb + (uint32_t)st * 2 * TBYTES;
        for (int it = tid; it < 1024; it += 256) {
            int r = it >> 3, q = it & 7;
            int node = row0 + r;
            uint32_t dst = (uint32_t)(r * TSTRIDE + q * 8) * 2;
            size_t asrc = (size_t)node * 512 + kc * 64 + q * 8;
            uint32_t ok = (node < N_NODES) ? 16u : 0u;
            cp16(stb + dst, g_zh + asrc, ok);
            cp16(stb + TBYTES + dst, g_zl + asrc, ok);
        }
        CP_COMMIT();
    };
    auto issueB = [&](int kc) {
        uint32_t stb = sb + BBASE;
        for (int it = tid; it < 1024; it += 256) {
            int r = it >> 3, q = it & 7;
            size_t bsrc = (size_t)r * 512 + kc * 64 + q * 8;
            uint32_t dst = (uint32_t)(r * TSTRIDE + q * 8) * 2;
            cp16(stb + dst, g_Uh + bsrc, 16);
            cp16(stb + TBYTES + dst, g_Ul + bsrc, 16);
        }
        CP_COMMIT();
    };

    float acc[4][4][4];
    #pragma unroll
    for (int i = 0; i < 4; i++)
        #pragma unroll
        for (int j = 0; j < 4; j++)
            #pragma unroll
            for (int q = 0; q < 4; q++) acc[i][j][q] = 0.f;

    issueA(0, 0);
    for (int kc = 0; kc < 8; kc++) {
        // commit order: B(kc) first, then A(kc+1); wait_group(1) releases B(kc)+A(kc)
        issueB(kc);
        if (kc < 7) {
            issueA(kc + 1, (kc + 1) & 1);
            CP_WAIT(1);
        } else {
            CP_WAIT(0);
        }
        __syncthreads();
        uint32_t stb = (uint32_t)(kc & 1) * 2 * TBYTES;
        mma_tile(sb, stb, stb + TBYTES, BBASE, BBASE + TBYTES,
                 lA, lB, warp_m, warp_n, acc);
        __syncthreads();
    }

    float* S = (float*)sm;                 // [128][133]
    float* stats = (float*)(sm + 128 * 133 * 4);
    #pragma unroll
    for (int mf = 0; mf < 4; mf++) {
        int r_lo = warp_m * 64 + mf * 16 + (lane >> 2);
        #pragma unroll
        for (int half = 0; half < 2; half++) {
            int r = r_lo + half * 8;
            #pragma unroll
            for (int nf = 0; nf < 4; nf++) {
                int col = warp_n * 32 + nf * 8 + (lane & 3) * 2;
                S[r * 133 + col]     = acc[mf][nf][half * 2 + 0] + g_oconst[col];
                S[r * 133 + col + 1] = acc[mf][nf][half * 2 + 1] + g_oconst[col + 1];
            }
        }
    }
    __syncthreads();
    if (tid < 128) {
        float s = 0.f, q = 0.f;
        #pragma unroll 8
        for (int j = 0; j < 128; j++) {
            float v = S[tid * 133 + j];
            s += v; q += v * v;
        }
        float mu = s * (1.f / 128.f);
        float var = q * (1.f / 128.f) - mu * mu;
        stats[tid] = mu;
        stats[128 + tid] = rsqrtf(var + 1e-5f);
    }
    __syncthreads();
    for (int it = tid; it < 128 * 32; it += 256) {
        int r = it >> 5, j = (it & 31) * 4;
        int node = row0 + r;
        if (node >= N_NODES) continue;
        float mu = stats[r], rs = stats[128 + r];
        float4 o;
        o.x = (S[r * 133 + j + 0] - mu) * rs * __ldg(gamma + j + 0) + __ldg(beta + j + 0);
        o.y = (S[r * 133 + j + 1] - mu) * rs * __ldg(gamma + j + 1) + __ldg(beta + j + 1);
        o.z = (S[r * 133 + j + 2] - mu) * rs * __ldg(gamma + j + 2) + __ldg(beta + j + 2);
        o.w = (S[r * 133 + j + 3] - mu) * rs * __ldg(gamma + j + 3) + __ldg(beta + j + 3);
        *(float4*)(out + (size_t)node * 128 + j) = o;
    }
}

// ---------------- launcher (graph-capturable 3-way fork/join, persistent streams) ----------------
extern "C" void kernel_launch(void* const* d_in, const int* in_sizes, int n_in,
                              void* d_out, int out_size) {
    const float* x     = (const float*)d_in[0];
    const int*   ei0   = (const int*)d_in[1];
    const int*   ei1   = (const int*)d_in[2];
    const float* w_in  = (const float*)d_in[3];
    const float* b_in  = (const float*)d_in[4];
    const float* w_out = (const float*)d_in[5];
    const float* b_out = (const float*)d_in[6];
    const float* gamma = (const float*)d_in[7];
    const float* beta  = (const float*)d_in[8];
    float* out = (float*)d_out;

    static bool inited = false;
    static cudaStream_t s1, s2;
    static cudaEvent_t evFork, evJ1, evJ2;
    if (!inited) {
        cudaStreamCreateWithFlags(&s1, cudaStreamNonBlocking);
        cudaStreamCreateWithFlags(&s2, cudaStreamNonBlocking);
        cudaEventCreateWithFlags(&evFork, cudaEventDisableTiming);
        cudaEventCreateWithFlags(&evJ1, cudaEventDisableTiming);
        cudaEventCreateWithFlags(&evJ2, cudaEventDisableTiming);
        cudaFuncSetAttribute(gemm1_tc, cudaFuncAttributeMaxDynamicSharedMemorySize, GEMM_SMEM);
        cudaFuncSetAttribute(gemm2_tc, cudaFuncAttributeMaxDynamicSharedMemorySize, GEMM_SMEM);
        inited = true;
    }

    cudaEventRecord(evFork, 0);
    cudaStreamWaitEvent(s1, evFork, 0);
    cudaStreamWaitEvent(s2, evFork, 0);

    // branch A: edge set 0
    zero_kernel<<<(N_NODES + 255) / 256, 256, 0, s1>>>(0);
    hist_kernel<<<(N_EDGES + 255) / 256, 256, 0, s1>>>(ei0, 0);
    scan_kernel<<<1, 1024, 0, s1>>>(0);
    fill_kernel<<<(N_EDGES + 255) / 256, 256, 0, s1>>>(ei0, 0);
    agg_kernel<<<(N_NODES + 7) / 8, 256, 0, s1>>>(x, 0);
    cudaEventRecord(evJ1, s1);

    // branch B: edge set 1
    zero_kernel<<<(N_NODES + 255) / 256, 256, 0, s2>>>(1);
    hist_kernel<<<(N_EDGES + 255) / 256, 256, 0, s2>>>(ei1, 1);
    scan_kernel<<<1, 1024, 0, s2>>>(1);
    fill_kernel<<<(N_EDGES + 255) / 256, 256, 0, s2>>>(ei1, 1);
    agg_kernel<<<(N_NODES + 7) / 8, 256, 0, s2>>>(x, 1);
    cudaEventRecord(evJ2, s2);

    // branch C (main): weight folding + GEMM1
    precompute_kernel<<<(2 * 512 * 128 + 512 + 128 + 255) / 256, 256>>>(w_in, b_in, w_out, b_out);
    const int GB = (N_NODES + 127) / 128;  // 391
    gemm1_tc<<<GB, 256, GEMM_SMEM>>>(x);

    // join
    cudaStreamWaitEvent(0, evJ1, 0);
    cudaStreamWaitEvent(0, evJ2, 0);
    attn_kernel<<<(N_NODES + 7) / 8, 256>>>(x);
    gemm2_tc<<<GB, 256, GEMM_SMEM>>>(gamma, beta, out);
}

// round 15
// speedup vs baseline: 1.0547x; 1.0547x over previous
#include <cuda_runtime.h>
#include <cuda_bf16.h>
#include <cstdint>

#define N_NODES 50000
#define N_EDGES 800000
#define DIMS 128
#define HEADS 4
#define NBLK 49   // ceil(50000/1024)

// ---------------- scratch (__device__ globals: allocation-free) ----------------
__device__ int   g_cnt[2][N_NODES];
__device__ int   g_cur[2][N_NODES];
__device__ int   g_off[2][N_NODES + 1];
__device__ int   g_adj[2][N_EDGES];
__device__ int   g_bsum[2][64];
__device__ int   g_bpre[2][64];
__device__ float g_aggr[6ull * N_NODES * DIMS];            // planes: max0,min0,sum0,max1,min1,sum1
__device__ float g_m[(size_t)N_NODES * HEADS * DIMS];      // [node][h*128+j]
__device__ __nv_bfloat16 g_zh[(size_t)N_NODES * HEADS * DIMS];
__device__ __nv_bfloat16 g_zl[(size_t)N_NODES * HEADS * DIMS];
// folded weights (bf16 hi/lo split)
__device__ __nv_bfloat16 g_Bwh[512 * 128];  // [n][k]
__device__ __nv_bfloat16 g_Bwl[512 * 128];
__device__ __nv_bfloat16 g_Uh[128 * 512];   // [c][kk]
__device__ __nv_bfloat16 g_Ul[128 * 512];
__device__ float g_mconst[512];
__device__ float g_oconst[128];

// ---------------- warp MMA + async helpers (plain PTX, sm_80+) ----------------
__device__ __forceinline__ uint32_t smem_to_u32(const void* p) {
    uint32_t a;
    asm("{ .reg .u64 t; cvta.to.shared.u64 t, %1; cvt.u32.u64 %0, t; }" : "=r"(a) : "l"(p));
    return a;
}
__device__ __forceinline__ void ldsm4(uint32_t (&r)[4], uint32_t addr) {
    asm volatile("ldmatrix.sync.aligned.m8n8.x4.shared.b16 {%0,%1,%2,%3}, [%4];"
                 : "=r"(r[0]), "=r"(r[1]), "=r"(r[2]), "=r"(r[3]) : "r"(addr));
}
__device__ __forceinline__ void mma16816(float (&c)[4], const uint32_t (&a)[4],
                                         uint32_t b0, uint32_t b1) {
    asm volatile("mma.sync.aligned.m16n8k16.row.col.f32.bf16.bf16.f32 "
                 "{%0,%1,%2,%3}, {%4,%5,%6,%7}, {%8,%9}, {%0,%1,%2,%3};"
                 : "+f"(c[0]), "+f"(c[1]), "+f"(c[2]), "+f"(c[3])
                 : "r"(a[0]), "r"(a[1]), "r"(a[2]), "r"(a[3]), "r"(b0), "r"(b1));
}
__device__ __forceinline__ uint32_t pack_bf16(__nv_bfloat16 a, __nv_bfloat16 b) {
    __nv_bfloat162 t = __halves2bfloat162(a, b);
    return *(uint32_t*)&t;
}
__device__ __forceinline__ void cp16(uint32_t smem_addr, const void* gptr, uint32_t srcsize) {
    asm volatile("cp.async.cg.shared.global [%0], [%1], 16, %2;"
                 :: "r"(smem_addr), "l"(gptr), "r"(srcsize) : "memory");
}
#define CP_COMMIT() asm volatile("cp.async.commit_group;" ::: "memory")
#define CP_WAIT(n)  asm volatile("cp.async.wait_group %0;" :: "n"(n) : "memory")

// SMEM tile geometry: [128 rows][64 k] bf16, row stride 72 (144B, ldmatrix conflict-free)
#define TSTRIDE 72
#define TBYTES  (128 * TSTRIDE * 2)   // 18432
#define GEMM_SMEM (8 * TBYTES)        // 147456

// ---------------- CSR build (per edge set) ----------------
__global__ void zero_kernel(int set) {
    int t = blockIdx.x * blockDim.x + threadIdx.x;
    if (t < N_NODES) {
        g_cnt[set][t] = 0;
        g_cur[set][t] = 0;
    }
}
__global__ void hist_kernel(const int* __restrict__ ei, int set) {
    int e = blockIdx.x * blockDim.x + threadIdx.x;
    if (e >= N_EDGES) return;
    atomicAdd(&g_cnt[set][ei[N_EDGES + e]], 1);
}
// 3-phase parallel scan
__global__ void scanA_kernel(int set) {
    __shared__ int sw[32];
    const int tid = threadIdx.x, lane = tid & 31, wid = tid >> 5;
    int i = blockIdx.x * 1024 + tid;
    int v = (i < N_NODES) ? g_cnt[set][i] : 0;
    #pragma unroll
    for (int o = 16; o; o >>= 1) v += __shfl_xor_sync(0xffffffffu, v, o);
    if (lane == 0) sw[wid] = v;
    __syncthreads();
    if (wid == 0) {
        int t = sw[lane];
        #pragma unroll
        for (int o = 16; o; o >>= 1) t += __shfl_xor_sync(0xffffffffu, t, o);
        if (lane == 0) g_bsum[set][blockIdx.x] = t;
    }
}
__global__ void scanB_kernel(int set) {
    __shared__ int s[64];
    const int tid = threadIdx.x;   // 64 threads
    int v = (tid < NBLK) ? g_bsum[set][tid] : 0;
    s[tid] = v;
    __syncthreads();
    #pragma unroll
    for (int o = 1; o < 64; o <<= 1) {
        int t = (tid >= o) ? s[tid - o] : 0;
        __syncthreads();
        s[tid] += t;
        __syncthreads();
    }
    if (tid < NBLK) g_bpre[set][tid] = s[tid] - v;   // exclusive prefix
}
__global__ void scanC_kernel(int set) {
    __shared__ int sw[32];
    const int tid = threadIdx.x, lane = tid & 31, wid = tid >> 5;
    int i = blockIdx.x * 1024 + tid;
    int v = (i < N_NODES) ? g_cnt[set][i] : 0;
    int incl = v;
    #pragma unroll
    for (int o = 1; o < 32; o <<= 1) {
        int t = __shfl_up_sync(0xffffffffu, incl, o);
        if (lane >= o) incl += t;
    }
    if (lane == 31) sw[wid] = incl;
    __syncthreads();
    if (wid == 0) {
        int t = sw[lane];
        #pragma unroll
        for (int o = 1; o < 32; o <<= 1) {
            int u = __shfl_up_sync(0xffffffffu, t, o);
            if (lane >= o) t += u;
        }
        sw[lane] = t;
    }
    __syncthreads();
    int add = (wid > 0) ? sw[wid - 1] : 0;
    if (i < N_NODES) g_off[set][i + 1] = g_bpre[set][blockIdx.x] + add + incl;
    if (i == 0) g_off[set][0] = 0;
}
__global__ void fill_kernel(const int* __restrict__ ei, int set) {
    int e = blockIdx.x * blockDim.x + threadIdx.x;
    if (e >= N_EDGES) return;
    int s = ei[e], d = ei[N_EDGES + e];
    int p = atomicAdd(&g_cur[set][d], 1);
    g_adj[set][g_off[set][d] + p] = s;
}

// ---------------- warp-per-node gather + max/min/sum (per set, 4-wide MLP) ----------------
__device__ __forceinline__ void acc3(float4& vmax, float4& vmin, float4& vsum, const float4 v) {
    vmax.x = fmaxf(vmax.x, v.x); vmax.y = fmaxf(vmax.y, v.y);
    vmax.z = fmaxf(vmax.z, v.z); vmax.w = fmaxf(vmax.w, v.w);
    vmin.x = fminf(vmin.x, v.x); vmin.y = fminf(vmin.y, v.y);
    vmin.z = fminf(vmin.z, v.z); vmin.w = fminf(vmin.w, v.w);
    vsum.x += v.x; vsum.y += v.y; vsum.z += v.z; vsum.w += v.w;
}
__global__ void agg_kernel(const float* __restrict__ x, int set) {
    int gw = (blockIdx.x * blockDim.x + threadIdx.x) >> 5;
    if (gw >= N_NODES) return;
    const int lane = threadIdx.x & 31;
    const int node = gw;
    const int beg = g_off[set][node], end = g_off[set][node + 1];
    const int* __restrict__ adj = g_adj[set];
    const size_t lo = (size_t)lane * 4;

    float4 vmax = make_float4(-3.402823466e38f, -3.402823466e38f, -3.402823466e38f, -3.402823466e38f);
    float4 vmin = make_float4( 3.402823466e38f,  3.402823466e38f,  3.402823466e38f,  3.402823466e38f);
    float4 vsum = make_float4(0.f, 0.f, 0.f, 0.f);

    int i = beg;
    for (; i + 4 <= end; i += 4) {
        int s0 = __ldg(adj + i + 0), s1 = __ldg(adj + i + 1);
        int s2 = __ldg(adj + i + 2), s3 = __ldg(adj + i + 3);
        float4 v0 = *(const float4*)(x + (size_t)s0 * DIMS + lo);
        float4 v1 = *(const float4*)(x + (size_t)s1 * DIMS + lo);
        float4 v2 = *(const float4*)(x + (size_t)s2 * DIMS + lo);
        float4 v3 = *(const float4*)(x + (size_t)s3 * DIMS + lo);
        acc3(vmax, vmin, vsum, v0);
        acc3(vmax, vmin, vsum, v1);
        acc3(vmax, vmin, vsum, v2);
        acc3(vmax, vmin, vsum, v3);
    }
    for (; i < end; i++) {
        int s = __ldg(adj + i);
        float4 v = *(const float4*)(x + (size_t)s * DIMS + lo);
        acc3(vmax, vmin, vsum, v);
    }

    const size_t plane = (size_t)N_NODES * DIMS;
    size_t base = ((size_t)(set * 3) * N_NODES + node) * DIMS + lo;
    if (end > beg) {
        *(float4*)(g_aggr + base)             = vmax;
        *(float4*)(g_aggr + base + plane)     = vmin;
        *(float4*)(g_aggr + base + 2 * plane) = vsum;
    } else {
        float4 z = make_float4(0.f, 0.f, 0.f, 0.f);
        *(float4*)(g_aggr + base)             = z;
        *(float4*)(g_aggr + base + plane)     = z;
        *(float4*)(g_aggr + base + 2 * plane) = z;
    }
}

// ---------------- fold weights: Bw, U, m_const, out_const ----------------
__global__ void precompute_kernel(const float* __restrict__ w_in,
                                  const float* __restrict__ b_in,
                                  const float* __restrict__ w_out,
                                  const float* __restrict__ b_out) {
    int t = blockIdx.x * blockDim.x + threadIdx.x;
    if (t < 512 * 128) {                    // Bw[n][k]
        int n = t >> 7, k = t & 127;
        int h = n >> 7, j = n & 127;
        float s = 0.f;
        #pragma unroll 8
        for (int i = 0; i < 32; i++)
            s += w_in[(size_t)(h * 32 + i) * 128 + k] * w_in[(size_t)(128 + h * 32 + i) * 128 + j];
        __nv_bfloat16 hi = __float2bfloat16(s);
        g_Bwh[t] = hi;
        g_Bwl[t] = __float2bfloat16(s - __bfloat162float(hi));
    } else if (t < 2 * 512 * 128) {         // U[c][kk]
        int u = t - 512 * 128;
        int c = u >> 9, kk = u & 511;
        int h = kk >> 7, d = kk & 127;
        float s = 0.f;
        #pragma unroll 8
        for (int i = 0; i < 32; i++)
            s += w_out[(size_t)c * 128 + h * 32 + i] * w_in[(size_t)(256 + h * 32 + i) * 128 + d];
        __nv_bfloat16 hi = __float2bfloat16(s);
        g_Uh[u] = hi;
        g_Ul[u] = __float2bfloat16(s - __bfloat162float(hi));
    } else if (t < 2 * 512 * 128 + 512) {   // m_const
        int n = t - 2 * 512 * 128;
        int h = n >> 7, j = n & 127;
        float s = 0.f;
        for (int i = 0; i < 32; i++)
            s += b_in[h * 32 + i] * w_in[(size_t)(128 + h * 32 + i) * 128 + j];
        g_mconst[n] = s;
    } else if (t < 2 * 512 * 128 + 512 + 128) {  // out_const
        int c = t - 2 * 512 * 128 - 512;
        float s = b_out[c];
        for (int n = 0; n < 128; n++)
            s += w_out[(size_t)c * 128 + n] * b_in[256 + n];
        g_oconst[c] = s;
    }
}

// per-lane ldmatrix source offsets (bytes) within a [*, TSTRIDE] bf16 tile
__device__ __forceinline__ uint32_t laneA_off(int lane) {
    int row = (lane < 16) ? lane : (lane - 16);
    int col = (lane < 16) ? 0 : 8;
    return (uint32_t)(row * TSTRIDE + col) * 2;
}
__device__ __forceinline__ uint32_t laneB_off(int lane) {
    int g = lane >> 3, r = lane & 7;
    int row = (g == 0 || g == 1) ? r : (8 + r);
    int col = (g == 1 || g == 3) ? 8 : 0;
    return (uint32_t)(row * TSTRIDE + col) * 2;
}
__device__ __forceinline__ void store_split4(char* base_h, char* base_l, int r, int k4, float4 v) {
    __nv_bfloat16 h0 = __float2bfloat16(v.x), h1 = __float2bfloat16(v.y);
    __nv_bfloat16 h2 = __float2bfloat16(v.z), h3 = __float2bfloat16(v.w);
    __nv_bfloat16 l0 = __float2bfloat16(v.x - __bfloat162float(h0));
    __nv_bfloat16 l1 = __float2bfloat16(v.y - __bfloat162float(h1));
    __nv_bfloat16 l2 = __float2bfloat16(v.z - __bfloat162float(h2));
    __nv_bfloat16 l3 = __float2bfloat16(v.w - __bfloat162float(h3));
    uint2 ph = make_uint2(pack_bf16(h0, h1), pack_bf16(h2, h3));
    uint2 pl = make_uint2(pack_bf16(l0, l1), pack_bf16(l2, l3));
    uint32_t off = (uint32_t)(r * TSTRIDE + k4 * 4) * 2;
    *(uint2*)(base_h + off) = ph;
    *(uint2*)(base_l + off) = pl;
}

// warp-tile MMA on one (A,B) smem tile pair with 3-pass hi/lo
__device__ __forceinline__ void mma_tile(uint32_t sb, uint32_t offAH, uint32_t offAL,
                                         uint32_t offBH, uint32_t offBL,
                                         uint32_t lA, uint32_t lB,
                                         int warp_m, int warp_n, float (&acc)[4][4][4]) {
    #pragma unroll
    for (int pass = 0; pass < 3; pass++) {
        const uint32_t Abase = sb + ((pass == 2) ? offAL : offAH);
        const uint32_t Bbase = sb + ((pass == 1) ? offBL : offBH);
        #pragma unroll
        for (int ks = 0; ks < 4; ks++) {
            uint32_t a[4][4];
            #pragma unroll
            for (int mf = 0; mf < 4; mf++)
                ldsm4(a[mf], Abase + lA + (uint32_t)((warp_m * 64 + mf * 16) * TSTRIDE + ks * 16) * 2);
            uint32_t b[2][4];
            #pragma unroll
            for (int nf2 = 0; nf2 < 2; nf2++)
                ldsm4(b[nf2], Bbase + lB + (uint32_t)((warp_n * 32 + nf2 * 16) * TSTRIDE + ks * 16) * 2);
            #pragma unroll
            for (int mf = 0; mf < 4; mf++)
                #pragma unroll
                for (int nf = 0; nf < 4; nf++)
                    mma16816(acc[mf][nf], a[mf], b[nf >> 1][(nf & 1) * 2], b[nf >> 1][(nf & 1) * 2 + 1]);
        }
    }
}

// ---------------- GEMM1 (HMMA, cp.async-pipelined B): m = x @ Bw^T + m_const ----------------
__global__ __launch_bounds__(256) void gemm1_tc(const float* __restrict__ x) {
    extern __shared__ char sm[];
    const int tid = threadIdx.x, wid = tid >> 5, lane = tid & 31;
    const int warp_m = wid >> 2, warp_n = wid & 3;
    const int row0 = blockIdx.x * 128;
    const uint32_t sb = smem_to_u32(sm);
    const uint32_t lA = laneA_off(lane), lB = laneB_off(lane);
    const uint32_t BBASE = 4 * TBYTES;

    for (int kc = 0; kc < 2; kc++) {
        char* ah = sm + (2 * kc) * TBYTES;
        char* al = sm + (2 * kc + 1) * TBYTES;
        for (int it = tid; it < 128 * 16; it += 256) {
            int r = it >> 4, q = it & 15;
            int node = row0 + r;
            float4 v = (node < N_NODES)
                ? *(const float4*)(x + (size_t)node * 128 + kc * 64 + q * 4)
                : make_float4(0.f, 0.f, 0.f, 0.f);
            store_split4(ah, al, r, q, v);
        }
    }

    auto issueB = [&](int s, int st) {
        int nc = s >> 1, kc = s & 1;
        uint32_t stb = sb + BBASE + (uint32_t)st * 2 * TBYTES;
        for (int it = tid; it < 1024; it += 256) {
            int r = it >> 3, q = it & 7;
            size_t src = (size_t)(nc * 128 + r) * 128 + kc * 64 + q * 8;
            uint32_t dst = (uint32_t)(r * TSTRIDE + q * 8) * 2;
            cp16(stb + dst, g_Bwh + src, 16);
            cp16(stb + TBYTES + dst, g_Bwl + src, 16);
        }
        CP_COMMIT();
    };

    issueB(0, 0);

    float acc[4][4][4];
    for (int s = 0; s < 8; s++) {
        int nc = s >> 1, kc = s & 1;
        if (kc == 0) {
            #pragma unroll
            for (int i = 0; i < 4; i++)
                #pragma unroll
                for (int j = 0; j < 4; j++)
                    #pragma unroll
                    for (int q = 0; q < 4; q++) acc[i][j][q] = 0.f;
        }
        if (s < 7) issueB(s + 1, (s + 1) & 1);
        if (s < 7) { CP_WAIT(1); } else { CP_WAIT(0); }
        __syncthreads();

        uint32_t offAH = (uint32_t)(2 * kc) * TBYTES;
        uint32_t offAL = offAH + TBYTES;
        uint32_t offBH = BBASE + (uint32_t)(s & 1) * 2 * TBYTES;
        uint32_t offBL = offBH + TBYTES;
        mma_tile(sb, offAH, offAL, offBH, offBL, lA, lB, warp_m, warp_n, acc);
        __syncthreads();

        if (kc == 1) {
            #pragma unroll
            for (int mf = 0; mf < 4; mf++) {
                int r_lo = row0 + warp_m * 64 + mf * 16 + (lane >> 2);
                #pragma unroll
                for (int half = 0; half < 2; half++) {
                    int node = r_lo + half * 8;
                    if (node >= N_NODES) continue;
                    #pragma unroll
                    for (int nf = 0; nf < 4; nf++) {
                        int col = nc * 128 + warp_n * 32 + nf * 8 + (lane & 3) * 2;
                        float2 o;
                        o.x = acc[mf][nf][half * 2 + 0] + g_mconst[col];
                        o.y = acc[mf][nf][half * 2 + 1] + g_mconst[col + 1];
                        *(float2*)(g_m + (size_t)node * 512 + col) = o;
                    }
                }
            }
        }
    }
}

// ---------------- scores + softmax + z (warp per node; z written as bf16 hi/lo) ----------------
__device__ __forceinline__ float dot4(const float4 a, const float4 b) {
    return a.x * b.x + a.y * b.y + a.z * b.z + a.w * b.w;
}
__device__ __forceinline__ void axpy4(float4& z, const float4 v, float s) {
    z.x += v.x * s; z.y += v.y * s; z.z += v.z * s; z.w += v.w * s;
}
__global__ void attn_kernel(const float* __restrict__ x) {
    int gw = (blockIdx.x * blockDim.x + threadIdx.x) >> 5;
    if (gw >= N_NODES) return;
    const int lane = threadIdx.x & 31;
    const int node = gw;
    const size_t rb = (size_t)node * DIMS + lane * 4;
    const size_t plane = (size_t)N_NODES * DIMS;

    float4 vx = *(const float4*)(x + rb);
    float4 av[6];
    #pragma unroll
    for (int p = 0; p < 6; p++) av[p] = *(const float4*)(g_aggr + p * plane + rb);
    float4 vm[4];
    const size_t mb = (size_t)node * (HEADS * DIMS) + lane * 4;
    #pragma unroll
    for (int h = 0; h < HEADS; h++) vm[h] = *(const float4*)(g_m + mb + h * DIMS);

    float dt[4][7];
    #pragma unroll
    for (int h = 0; h < 4; h++) {
        dt[h][0] = dot4(vm[h], vx);
        #pragma unroll
        for (int p = 0; p < 6; p++) dt[h][1 + p] = dot4(vm[h], av[p]);
    }
    #pragma unroll
    for (int h = 0; h < 4; h++)
        #pragma unroll
        for (int v = 0; v < 7; v++) {
            float t = dt[h][v];
            #pragma unroll
            for (int o = 16; o; o >>= 1) t += __shfl_xor_sync(0xffffffffu, t, o);
            dt[h][v] = t;
        }

    const int cnt0 = g_cnt[0][node], cnt1 = g_cnt[1][node];
    const float c0 = (float)cnt0, c1 = (float)cnt1;
    const float sc = 0.17677669529663687f;  // 1/sqrt(32)

    #pragma unroll
    for (int h = 0; h < 4; h++) {
        float s0 = dt[h][0] * sc;
        float mx = s0;
        float a0 = 0.f, b0 = 0.f, u0 = 0.f, n0 = 0.f;
        float a1 = 0.f, b1 = 0.f, u1 = 0.f, n1 = 0.f;
        if (cnt0) {
            a0 = dt[h][1] * sc; b0 = dt[h][2] * sc; u0 = dt[h][3] * sc; n0 = u0 / c0;
            mx = fmaxf(mx, fmaxf(fmaxf(a0, b0), fmaxf(u0, n0)));
        }
        if (cnt1) {
            a1 = dt[h][4] * sc; b1 = dt[h][5] * sc; u1 = dt[h][6] * sc; n1 = u1 / c1;
            mx = fmaxf(mx, fmaxf(fmaxf(a1, b1), fmaxf(u1, n1)));
        }
        float eself = __expf(s0 - mx);
        float den = eself;
        float wm0 = 0.f, wn0 = 0.f, ws0 = 0.f, wm1 = 0.f, wn1 = 0.f, ws1 = 0.f;
        if (cnt0) {
            float e1 = __expf(a0 - mx), e2 = __expf(b0 - mx);
            float e3 = __expf(u0 - mx), e4 = __expf(n0 - mx);
            den += e1 + e2 + e3 + e4;
            wm0 = e1; wn0 = e2; ws0 = e3 + e4 / c0;
        }
        if (cnt1) {
            float e1 = __expf(a1 - mx), e2 = __expf(b1 - mx);
            float e3 = __expf(u1 - mx), e4 = __expf(n1 - mx);
            den += e1 + e2 + e3 + e4;
            wm1 = e1; wn1 = e2; ws1 = e3 + e4 / c1;
        }
        float inv = 1.f / den;
        float4 z = make_float4(0.f, 0.f, 0.f, 0.f);
        axpy4(z, vx, eself * inv);
        if (cnt0) { axpy4(z, av[0], wm0 * inv); axpy4(z, av[1], wn0 * inv); axpy4(z, av[2], ws0 * inv); }
        if (cnt1) { axpy4(z, av[3], wm1 * inv); axpy4(z, av[4], wn1 * inv); axpy4(z, av[5], ws1 * inv); }

        __nv_bfloat16 h0 = __float2bfloat16(z.x), h1 = __float2bfloat16(z.y);
        __nv_bfloat16 h2 = __float2bfloat16(z.z), h3 = __float2bfloat16(z.w);
        __nv_bfloat16 l0 = __float2bfloat16(z.x - __bfloat162float(h0));
        __nv_bfloat16 l1 = __float2bfloat16(z.y - __bfloat162float(h1));
        __nv_bfloat16 l2 = __float2bfloat16(z.z - __bfloat162float(h2));
        __nv_bfloat16 l3 = __float2bfloat16(z.w - __bfloat162float(h3));
        *(uint2*)(g_zh + mb + h * DIMS) = make_uint2(pack_bf16(h0, h1), pack_bf16(h2, h3));
        *(uint2*)(g_zl + mb + h * DIMS) = make_uint2(pack_bf16(l0, l1), pack_bf16(l2, l3));
    }
}

// ---------------- GEMM2 (HMMA, cp.async-pipelined A+B): out = LN(z @ U^T + out_const) ----------------
__global__ __launch_bounds__(256) void gemm2_tc(const float* __restrict__ gamma,
                                                const float* __restrict__ beta,
                                                float* __restrict__ out) {
    extern __shared__ char sm[];
    const int tid = threadIdx.x, wid = tid >> 5, lane = tid & 31;
    const int warp_m = wid >> 2, warp_n = wid & 3;
    const int row0 = blockIdx.x * 128;
    const uint32_t sb = smem_to_u32(sm);
    const uint32_t lA = laneA_off(lane), lB = laneB_off(lane);

    auto issue = [&](int kc, int st) {
        uint32_t stb = sb + (uint32_t)st * 4 * TBYTES;
        for (int it = tid; it < 1024; it += 256) {
            int r = it >> 3, q = it & 7;
            int node = row0 + r;
            uint32_t dst = (uint32_t)(r * TSTRIDE + q * 8) * 2;
            size_t asrc = (size_t)node * 512 + kc * 64 + q * 8;
            uint32_t ok = (node < N_NODES) ? 16u : 0u;
            cp16(stb + dst, g_zh + asrc, ok);
            cp16(stb + TBYTES + dst, g_zl + asrc, ok);
            size_t bsrc = (size_t)r * 512 + kc * 64 + q * 8;
            cp16(stb + 2 * TBYTES + dst, g_Uh + bsrc, 16);
            cp16(stb + 3 * TBYTES + dst, g_Ul + bsrc, 16);
        }
        CP_COMMIT();
    };

    float acc[4][4][4];
    #pragma unroll
    for (int i = 0; i < 4; i++)
        #pragma unroll
        for (int j = 0; j < 4; j++)
            #pragma unroll
            for (int q = 0; q < 4; q++) acc[i][j][q] = 0.f;

    issue(0, 0);
    for (int kc = 0; kc < 8; kc++) {
        if (kc < 7) issue(kc + 1, (kc + 1) & 1);
        if (kc < 7) { CP_WAIT(1); } else { CP_WAIT(0); }
        __syncthreads();
        uint32_t stb = (uint32_t)(kc & 1) * 4 * TBYTES;
        mma_tile(sb, stb, stb + TBYTES, stb + 2 * TBYTES, stb + 3 * TBYTES,
                 lA, lB, warp_m, warp_n, acc);
        __syncthreads();
    }

    float* S = (float*)sm;                 // [128][133]
    float* stats = (float*)(sm + 128 * 133 * 4);
    #pragma unroll
    for (int mf = 0; mf < 4; mf++) {
        int r_lo = warp_m * 64 + mf * 16 + (lane >> 2);
        #pragma unroll
        for (int half = 0; half < 2; half++) {
            int r = r_lo + half * 8;
            #pragma unroll
            for (int nf = 0; nf < 4; nf++) {
                int col = warp_n * 32 + nf * 8 + (lane & 3) * 2;
                S[r * 133 + col]     = acc[mf][nf][half * 2 + 0] + g_oconst[col];
                S[r * 133 + col + 1] = acc[mf][nf][half * 2 + 1] + g_oconst[col + 1];
            }
        }
    }
    __syncthreads();
    if (tid < 128) {
        float s = 0.f, q = 0.f;
        #pragma unroll 8
        for (int j = 0; j < 128; j++) {
            float v = S[tid * 133 + j];
            s += v; q += v * v;
        }
        float mu = s * (1.f / 128.f);
        float var = q * (1.f / 128.f) - mu * mu;
        stats[tid] = mu;
        stats[128 + tid] = rsqrtf(var + 1e-5f);
    }
    __syncthreads();
    for (int it = tid; it < 128 * 32; it += 256) {
        int r = it >> 5, j = (it & 31) * 4;
        int node = row0 + r;
        if (node >= N_NODES) continue;
        float mu = stats[r], rs = stats[128 + r];
        float4 o;
        o.x = (S[r * 133 + j + 0] - mu) * rs * __ldg(gamma + j + 0) + __ldg(beta + j + 0);
        o.y = (S[r * 133 + j + 1] - mu) * rs * __ldg(gamma + j + 1) + __ldg(beta + j + 1);
        o.z = (S[r * 133 + j + 2] - mu) * rs * __ldg(gamma + j + 2) + __ldg(beta + j + 2);
        o.w = (S[r * 133 + j + 3] - mu) * rs * __ldg(gamma + j + 3) + __ldg(beta + j + 3);
        *(float4*)(out + (size_t)node * 128 + j) = o;
    }
}

// ---------------- launcher (graph-capturable 3-way fork/join, persistent streams) ----------------
extern "C" void kernel_launch(void* const* d_in, const int* in_sizes, int n_in,
                              void* d_out, int out_size) {
    const float* x     = (const float*)d_in[0];
    const int*   ei0   = (const int*)d_in[1];
    const int*   ei1   = (const int*)d_in[2];
    const float* w_in  = (const float*)d_in[3];
    const float* b_in  = (const float*)d_in[4];
    const float* w_out = (const float*)d_in[5];
    const float* b_out = (const float*)d_in[6];
    const float* gamma = (const float*)d_in[7];
    const float* beta  = (const float*)d_in[8];
    float* out = (float*)d_out;

    static bool inited = false;
    static cudaStream_t s1, s2;
    static cudaEvent_t evFork, evJ1, evJ2;
    if (!inited) {
        cudaStreamCreateWithFlags(&s1, cudaStreamNonBlocking);
        cudaStreamCreateWithFlags(&s2, cudaStreamNonBlocking);
        cudaEventCreateWithFlags(&evFork, cudaEventDisableTiming);
        cudaEventCreateWithFlags(&evJ1, cudaEventDisableTiming);
        cudaEventCreateWithFlags(&evJ2, cudaEventDisableTiming);
        cudaFuncSetAttribute(gemm1_tc, cudaFuncAttributeMaxDynamicSharedMemorySize, GEMM_SMEM);
        cudaFuncSetAttribute(gemm2_tc, cudaFuncAttributeMaxDynamicSharedMemorySize, GEMM_SMEM);
        inited = true;
    }

    cudaEventRecord(evFork, 0);
    cudaStreamWaitEvent(s1, evFork, 0);
    cudaStreamWaitEvent(s2, evFork, 0);

    // branch A: edge set 0
    zero_kernel<<<(N_NODES + 255) / 256, 256, 0, s1>>>(0);
    hist_kernel<<<(N_EDGES + 255) / 256, 256, 0, s1>>>(ei0, 0);
    scanA_kernel<<<NBLK, 1024, 0, s1>>>(0);
    scanB_kernel<<<1, 64, 0, s1>>>(0);
    scanC_kernel<<<NBLK, 1024, 0, s1>>>(0);
    fill_kernel<<<(N_EDGES + 255) / 256, 256, 0, s1>>>(ei0, 0);
    agg_kernel<<<(N_NODES + 7) / 8, 256, 0, s1>>>(x, 0);
    cudaEventRecord(evJ1, s1);

    // branch B: edge set 1
    zero_kernel<<<(N_NODES + 255) / 256, 256, 0, s2>>>(1);
    hist_kernel<<<(N_EDGES + 255) / 256, 256, 0, s2>>>(ei1, 1);
    scanA_kernel<<<NBLK, 1024, 0, s2>>>(1);
    scanB_kernel<<<1, 64, 0, s2>>>(1);
    scanC_kernel<<<NBLK, 1024, 0, s2>>>(1);
    fill_kernel<<<(N_EDGES + 255) / 256, 256, 0, s2>>>(ei1, 1);
    agg_kernel<<<(N_NODES + 7) / 8, 256, 0, s2>>>(x, 1);
    cudaEventRecord(evJ2, s2);

    // branch C (main): weight folding + GEMM1
    precompute_kernel<<<(2 * 512 * 128 + 512 + 128 + 255) / 256, 256>>>(w_in, b_in, w_out, b_out);
    const int GB = (N_NODES + 127) / 128;  // 391
    gemm1_tc<<<GB, 256, GEMM_SMEM>>>(x);

    // join
    cudaStreamWaitEvent(0, evJ1, 0);
    cudaStreamWaitEvent(0, evJ2, 0);
    attn_kernel<<<(N_NODES + 7) / 8, 256>>>(x);
    gemm2_tc<<<GB, 256, GEMM_SMEM>>>(gamma, beta, out);
}

// round 16
// speedup vs baseline: 1.0678x; 1.0124x over previous
#include <cuda_runtime.h>
#include <cuda_bf16.h>
#include <cstdint>

#define N_NODES 50000
#define N_EDGES 800000
#define DIMS 128
#define HEADS 4
#define NBLK 49   // ceil(50000/1024)

// ---------------- scratch (__device__ globals: allocation-free) ----------------
__device__ int   g_cnt[2][N_NODES];
__device__ int   g_cur[2][N_NODES];     // absolute write cursors (seeded by scanC)
__device__ int   g_off[2][N_NODES + 1];
__device__ int   g_adj[2][N_EDGES];
__device__ int   g_bsum[2][64];
__device__ float g_aggr[6ull * N_NODES * DIMS];            // planes: max0,min0,sum0,max1,min1,sum1
__device__ float g_m[(size_t)N_NODES * HEADS * DIMS];      // [node][h*128+j]
__device__ __nv_bfloat16 g_zh[(size_t)N_NODES * HEADS * DIMS];
__device__ __nv_bfloat16 g_zl[(size_t)N_NODES * HEADS * DIMS];
// folded weights (bf16 hi/lo split)
__device__ __nv_bfloat16 g_Bwh[512 * 128];  // [n][k]
__device__ __nv_bfloat16 g_Bwl[512 * 128];
__device__ __nv_bfloat16 g_Uh[128 * 512];   // [c][kk]
__device__ __nv_bfloat16 g_Ul[128 * 512];
__device__ float g_mconst[512];
__device__ float g_oconst[128];

// ---------------- warp MMA + async helpers (plain PTX, sm_80+) ----------------
__device__ __forceinline__ uint32_t smem_to_u32(const void* p) {
    uint32_t a;
    asm("{ .reg .u64 t; cvta.to.shared.u64 t, %1; cvt.u32.u64 %0, t; }" : "=r"(a) : "l"(p));
    return a;
}
__device__ __forceinline__ void ldsm4(uint32_t (&r)[4], uint32_t addr) {
    asm volatile("ldmatrix.sync.aligned.m8n8.x4.shared.b16 {%0,%1,%2,%3}, [%4];"
                 : "=r"(r[0]), "=r"(r[1]), "=r"(r[2]), "=r"(r[3]) : "r"(addr));
}
__device__ __forceinline__ void mma16816(float (&c)[4], const uint32_t (&a)[4],
                                         uint32_t b0, uint32_t b1) {
    asm volatile("mma.sync.aligned.m16n8k16.row.col.f32.bf16.bf16.f32 "
                 "{%0,%1,%2,%3}, {%4,%5,%6,%7}, {%8,%9}, {%0,%1,%2,%3};"
                 : "+f"(c[0]), "+f"(c[1]), "+f"(c[2]), "+f"(c[3])
                 : "r"(a[0]), "r"(a[1]), "r"(a[2]), "r"(a[3]), "r"(b0), "r"(b1));
}
__device__ __forceinline__ uint32_t pack_bf16(__nv_bfloat16 a, __nv_bfloat16 b) {
    __nv_bfloat162 t = __halves2bfloat162(a, b);
    return *(uint32_t*)&t;
}
__device__ __forceinline__ void cp16(uint32_t smem_addr, const void* gptr, uint32_t srcsize) {
    asm volatile("cp.async.cg.shared.global [%0], [%1], 16, %2;"
                 :: "r"(smem_addr), "l"(gptr), "r"(srcsize) : "memory");
}
#define CP_COMMIT() asm volatile("cp.async.commit_group;" ::: "memory")
#define CP_WAIT(n)  asm volatile("cp.async.wait_group %0;" :: "n"(n) : "memory")

// SMEM tile geometry: [128 rows][64 k] bf16, row stride 72 (144B, ldmatrix conflict-free)
#define TSTRIDE 72
#define TBYTES  (128 * TSTRIDE * 2)   // 18432
#define GEMM_SMEM (8 * TBYTES)        // 147456

// ---------------- CSR build (per edge set) ----------------
__global__ void zero_kernel(int set) {
    int t = blockIdx.x * blockDim.x + threadIdx.x;
    if (t < N_NODES) g_cnt[set][t] = 0;
}
__global__ void hist_kernel(const int* __restrict__ ei, int set) {
    int e = blockIdx.x * blockDim.x + threadIdx.x;
    if (e >= N_EDGES) return;
    atomicAdd(&g_cnt[set][ei[N_EDGES + e]], 1);
}
// phase A: per-block sums
__global__ void scanA_kernel(int set) {
    __shared__ int sw[32];
    const int tid = threadIdx.x, lane = tid & 31, wid = tid >> 5;
    int i = blockIdx.x * 1024 + tid;
    int v = (i < N_NODES) ? g_cnt[set][i] : 0;
    #pragma unroll
    for (int o = 16; o; o >>= 1) v += __shfl_xor_sync(0xffffffffu, v, o);
    if (lane == 0) sw[wid] = v;
    __syncthreads();
    if (wid == 0) {
        int t = sw[lane];
        #pragma unroll
        for (int o = 16; o; o >>= 1) t += __shfl_xor_sync(0xffffffffu, t, o);
        if (lane == 0) g_bsum[set][blockIdx.x] = t;
    }
}
// phase C: per-block scan; block prefix computed inline; also seeds g_cur = off
__global__ void scanC_kernel(int set) {
    __shared__ int sw[32];
    __shared__ int blockPre;
    const int tid = threadIdx.x, lane = tid & 31, wid = tid >> 5;
    if (wid == 0) {
        int j0 = lane, j1 = lane + 32;
        int v = 0;
        if (j0 < blockIdx.x && j0 < NBLK) v += g_bsum[set][j0];
        if (j1 < blockIdx.x && j1 < NBLK) v += g_bsum[set][j1];
        #pragma unroll
        for (int o = 16; o; o >>= 1) v += __shfl_xor_sync(0xffffffffu, v, o);
        if (lane == 0) blockPre = v;
    }
    int i = blockIdx.x * 1024 + tid;
    int v = (i < N_NODES) ? g_cnt[set][i] : 0;
    int incl = v;
    #pragma unroll
    for (int o = 1; o < 32; o <<= 1) {
        int t = __shfl_up_sync(0xffffffffu, incl, o);
        if (lane >= o) incl += t;
    }
    if (lane == 31) sw[wid] = incl;
    __syncthreads();
    if (wid == 0) {
        int t = sw[lane];
        #pragma unroll
        for (int o = 1; o < 32; o <<= 1) {
            int u = __shfl_up_sync(0xffffffffu, t, o);
            if (lane >= o) t += u;
        }
        sw[lane] = t;
    }
    __syncthreads();
    int add = (wid > 0) ? sw[wid - 1] : 0;
    if (i < N_NODES) {
        int off_end = blockPre + add + incl;
        g_off[set][i + 1] = off_end;
        g_cur[set][i] = off_end - v;   // exclusive prefix = write cursor
    }
    if (i == 0) g_off[set][0] = 0;
}
__global__ void fill_kernel(const int* __restrict__ ei, int set) {
    int e = blockIdx.x * blockDim.x + threadIdx.x;
    if (e >= N_EDGES) return;
    int s = ei[e], d = ei[N_EDGES + e];
    int p = atomicAdd(&g_cur[set][d], 1);
    g_adj[set][p] = s;
}

// ---------------- warp-per-node gather + max/min/sum (per set, 4-wide MLP) ----------------
__device__ __forceinline__ void acc3(float4& vmax, float4& vmin, float4& vsum, const float4 v) {
    vmax.x = fmaxf(vmax.x, v.x); vmax.y = fmaxf(vmax.y, v.y);
    vmax.z = fmaxf(vmax.z, v.z); vmax.w = fmaxf(vmax.w, v.w);
    vmin.x = fminf(vmin.x, v.x); vmin.y = fminf(vmin.y, v.y);
    vmin.z = fminf(vmin.z, v.z); vmin.w = fminf(vmin.w, v.w);
    vsum.x += v.x; vsum.y += v.y; vsum.z += v.z; vsum.w += v.w;
}
__global__ void agg_kernel(const float* __restrict__ x, int set) {
    int gw = (blockIdx.x * blockDim.x + threadIdx.x) >> 5;
    if (gw >= N_NODES) return;
    const int lane = threadIdx.x & 31;
    const int node = gw;
    const int beg = g_off[set][node], end = g_off[set][node + 1];
    const int* __restrict__ adj = g_adj[set];
    const size_t lo = (size_t)lane * 4;

    float4 vmax = make_float4(-3.402823466e38f, -3.402823466e38f, -3.402823466e38f, -3.402823466e38f);
    float4 vmin = make_float4( 3.402823466e38f,  3.402823466e38f,  3.402823466e38f,  3.402823466e38f);
    float4 vsum = make_float4(0.f, 0.f, 0.f, 0.f);

    int i = beg;
    for (; i + 4 <= end; i += 4) {
        int s0 = __ldg(adj + i + 0), s1 = __ldg(adj + i + 1);
        int s2 = __ldg(adj + i + 2), s3 = __ldg(adj + i + 3);
        float4 v0 = *(const float4*)(x + (size_t)s0 * DIMS + lo);
        float4 v1 = *(const float4*)(x + (size_t)s1 * DIMS + lo);
        float4 v2 = *(const float4*)(x + (size_t)s2 * DIMS + lo);
        float4 v3 = *(const float4*)(x + (size_t)s3 * DIMS + lo);
        acc3(vmax, vmin, vsum, v0);
        acc3(vmax, vmin, vsum, v1);
        acc3(vmax, vmin, vsum, v2);
        acc3(vmax, vmin, vsum, v3);
    }
    for (; i < end; i++) {
        int s = __ldg(adj + i);
        float4 v = *(const float4*)(x + (size_t)s * DIMS + lo);
        acc3(vmax, vmin, vsum, v);
    }

    const size_t plane = (size_t)N_NODES * DIMS;
    size_t base = ((size_t)(set * 3) * N_NODES + node) * DIMS + lo;
    if (end > beg) {
        *(float4*)(g_aggr + base)             = vmax;
        *(float4*)(g_aggr + base + plane)     = vmin;
        *(float4*)(g_aggr + base + 2 * plane) = vsum;
    } else {
        float4 z = make_float4(0.f, 0.f, 0.f, 0.f);
        *(float4*)(g_aggr + base)             = z;
        *(float4*)(g_aggr + base + plane)     = z;
        *(float4*)(g_aggr + base + 2 * plane) = z;
    }
}

// ---------------- fold weights: Bw, U, m_const, out_const ----------------
__global__ void precompute_kernel(const float* __restrict__ w_in,
                                  const float* __restrict__ b_in,
                                  const float* __restrict__ w_out,
                                  const float* __restrict__ b_out) {
    int t = blockIdx.x * blockDim.x + threadIdx.x;
    if (t < 512 * 128) {                    // Bw[n][k]
        int n = t >> 7, k = t & 127;
        int h = n >> 7, j = n & 127;
        float s = 0.f;
        #pragma unroll 8
        for (int i = 0; i < 32; i++)
            s += w_in[(size_t)(h * 32 + i) * 128 + k] * w_in[(size_t)(128 + h * 32 + i) * 128 + j];
        __nv_bfloat16 hi = __float2bfloat16(s);
        g_Bwh[t] = hi;
        g_Bwl[t] = __float2bfloat16(s - __bfloat162float(hi));
    } else if (t < 2 * 512 * 128) {         // U[c][kk]
        int u = t - 512 * 128;
        int c = u >> 9, kk = u & 511;
        int h = kk >> 7, d = kk & 127;
        float s = 0.f;
        #pragma unroll 8
        for (int i = 0; i < 32; i++)
            s += w_out[(size_t)c * 128 + h * 32 + i] * w_in[(size_t)(256 + h * 32 + i) * 128 + d];
        __nv_bfloat16 hi = __float2bfloat16(s);
        g_Uh[u] = hi;
        g_Ul[u] = __float2bfloat16(s - __bfloat162float(hi));
    } else if (t < 2 * 512 * 128 + 512) {   // m_const
        int n = t - 2 * 512 * 128;
        int h = n >> 7, j = n & 127;
        float s = 0.f;
        for (int i = 0; i < 32; i++)
            s += b_in[h * 32 + i] * w_in[(size_t)(128 + h * 32 + i) * 128 + j];
        g_mconst[n] = s;
    } else if (t < 2 * 512 * 128 + 512 + 128) {  // out_const
        int c = t - 2 * 512 * 128 - 512;
        float s = b_out[c];
        for (int n = 0; n < 128; n++)
            s += w_out[(size_t)c * 128 + n] * b_in[256 + n];
        g_oconst[c] = s;
    }
}

// per-lane ldmatrix source offsets (bytes) within a [*, TSTRIDE] bf16 tile
__device__ __forceinline__ uint32_t laneA_off(int lane) {
    int row = (lane < 16) ? lane : (lane - 16);
    int col = (lane < 16) ? 0 : 8;
    return (uint32_t)(row * TSTRIDE + col) * 2;
}
__device__ __forceinline__ uint32_t laneB_off(int lane) {
    int g = lane >> 3, r = lane & 7;
    int row = (g == 0 || g == 1) ? r : (8 + r);
    int col = (g == 1 || g == 3) ? 8 : 0;
    return (uint32_t)(row * TSTRIDE + col) * 2;
}
__device__ __forceinline__ void store_split4(char* base_h, char* base_l, int r, int k4, float4 v) {
    __nv_bfloat16 h0 = __float2bfloat16(v.x), h1 = __float2bfloat16(v.y);
    __nv_bfloat16 h2 = __float2bfloat16(v.z), h3 = __float2bfloat16(v.w);
    __nv_bfloat16 l0 = __float2bfloat16(v.x - __bfloat162float(h0));
    __nv_bfloat16 l1 = __float2bfloat16(v.y - __bfloat162float(h1));
    __nv_bfloat16 l2 = __float2bfloat16(v.z - __bfloat162float(h2));
    __nv_bfloat16 l3 = __float2bfloat16(v.w - __bfloat162float(h3));
    uint2 ph = make_uint2(pack_bf16(h0, h1), pack_bf16(h2, h3));
    uint2 pl = make_uint2(pack_bf16(l0, l1), pack_bf16(l2, l3));
    uint32_t off = (uint32_t)(r * TSTRIDE + k4 * 4) * 2;
    *(uint2*)(base_h + off) = ph;
    *(uint2*)(base_l + off) = pl;
}

// warp-tile MMA on one (A,B) smem tile pair with 3-pass hi/lo
__device__ __forceinline__ void mma_tile(uint32_t sb, uint32_t offAH, uint32_t offAL,
                                         uint32_t offBH, uint32_t offBL,
                                         uint32_t lA, uint32_t lB,
                                         int warp_m, int warp_n, float (&acc)[4][4][4]) {
    #pragma unroll
    for (int pass = 0; pass < 3; pass++) {
        const uint32_t Abase = sb + ((pass == 2) ? offAL : offAH);
        const uint32_t Bbase = sb + ((pass == 1) ? offBL : offBH);
        #pragma unroll
        for (int ks = 0; ks < 4; ks++) {
            uint32_t a[4][4];
            #pragma unroll
            for (int mf = 0; mf < 4; mf++)
                ldsm4(a[mf], Abase + lA + (uint32_t)((warp_m * 64 + mf * 16) * TSTRIDE + ks * 16) * 2);
            uint32_t b[2][4];
            #pragma unroll
            for (int nf2 = 0; nf2 < 2; nf2++)
                ldsm4(b[nf2], Bbase + lB + (uint32_t)((warp_n * 32 + nf2 * 16) * TSTRIDE + ks * 16) * 2);
            #pragma unroll
            for (int mf = 0; mf < 4; mf++)
                #pragma unroll
                for (int nf = 0; nf < 4; nf++)
                    mma16816(acc[mf][nf], a[mf], b[nf >> 1][(nf & 1) * 2], b[nf >> 1][(nf & 1) * 2 + 1]);
        }
    }
}

// ---------------- GEMM1 (HMMA, cp.async-pipelined B): m = x @ Bw^T + m_const ----------------
__global__ __launch_bounds__(256) void gemm1_tc(const float* __restrict__ x) {
    extern __shared__ char sm[];
    const int tid = threadIdx.x, wid = tid >> 5, lane = tid & 31;
    const int warp_m = wid >> 2, warp_n = wid & 3;
    const int row0 = blockIdx.x * 128;
    const uint32_t sb = smem_to_u32(sm);
    const uint32_t lA = laneA_off(lane), lB = laneB_off(lane);
    const uint32_t BBASE = 4 * TBYTES;

    for (int kc = 0; kc < 2; kc++) {
        char* ah = sm + (2 * kc) * TBYTES;
        char* al = sm + (2 * kc + 1) * TBYTES;
        for (int it = tid; it < 128 * 16; it += 256) {
            int r = it >> 4, q = it & 15;
            int node = row0 + r;
            float4 v = (node < N_NODES)
                ? *(const float4*)(x + (size_t)node * 128 + kc * 64 + q * 4)
                : make_float4(0.f, 0.f, 0.f, 0.f);
            store_split4(ah, al, r, q, v);
        }
    }

    auto issueB = [&](int s, int st) {
        int nc = s >> 1, kc = s & 1;
        uint32_t stb = sb + BBASE + (uint32_t)st * 2 * TBYTES;
        for (int it = tid; it < 1024; it += 256) {
            int r = it >> 3, q = it & 7;
            size_t src = (size_t)(nc * 128 + r) * 128 + kc * 64 + q * 8;
            uint32_t dst = (uint32_t)(r * TSTRIDE + q * 8) * 2;
            cp16(stb + dst, g_Bwh + src, 16);
            cp16(stb + TBYTES + dst, g_Bwl + src, 16);
        }
        CP_COMMIT();
    };

    issueB(0, 0);

    float acc[4][4][4];
    for (int s = 0; s < 8; s++) {
        int nc = s >> 1, kc = s & 1;
        if (kc == 0) {
            #pragma unroll
            for (int i = 0; i < 4; i++)
                #pragma unroll
                for (int j = 0; j < 4; j++)
                    #pragma unroll
                    for (int q = 0; q < 4; q++) acc[i][j][q] = 0.f;
        }
        if (s < 7) issueB(s + 1, (s + 1) & 1);
        if (s < 7) { CP_WAIT(1); } else { CP_WAIT(0); }
        __syncthreads();

        uint32_t offAH = (uint32_t)(2 * kc) * TBYTES;
        uint32_t offAL = offAH + TBYTES;
        uint32_t offBH = BBASE + (uint32_t)(s & 1) * 2 * TBYTES;
        uint32_t offBL = offBH + TBYTES;
        mma_tile(sb, offAH, offAL, offBH, offBL, lA, lB, warp_m, warp_n, acc);
        __syncthreads();

        if (kc == 1) {
            #pragma unroll
            for (int mf = 0; mf < 4; mf++) {
                int r_lo = row0 + warp_m * 64 + mf * 16 + (lane >> 2);
                #pragma unroll
                for (int half = 0; half < 2; half++) {
                    int node = r_lo + half * 8;
                    if (node >= N_NODES) continue;
                    #pragma unroll
                    for (int nf = 0; nf < 4; nf++) {
                        int col = nc * 128 + warp_n * 32 + nf * 8 + (lane & 3) * 2;
                        float2 o;
                        o.x = acc[mf][nf][half * 2 + 0] + g_mconst[col];
                        o.y = acc[mf][nf][half * 2 + 1] + g_mconst[col + 1];
                        *(float2*)(g_m + (size_t)node * 512 + col) = o;
                    }
                }
            }
        }
    }
}

// ---------------- scores + softmax + z (warp per node; z written as bf16 hi/lo) ----------------
__device__ __forceinline__ float dot4(const float4 a, const float4 b) {
    return a.x * b.x + a.y * b.y + a.z * b.z + a.w * b.w;
}
__device__ __forceinline__ void axpy4(float4& z, const float4 v, float s) {
    z.x += v.x * s; z.y += v.y * s; z.z += v.z * s; z.w += v.w * s;
}
__global__ void attn_kernel(const float* __restrict__ x) {
    int gw = (blockIdx.x * blockDim.x + threadIdx.x) >> 5;
    if (gw >= N_NODES) return;
    const int lane = threadIdx.x & 31;
    const int node = gw;
    const size_t rb = (size_t)node * DIMS + lane * 4;
    const size_t plane = (size_t)N_NODES * DIMS;

    float4 vx = *(const float4*)(x + rb);
    float4 av[6];
    #pragma unroll
    for (int p = 0; p < 6; p++) av[p] = *(const float4*)(g_aggr + p * plane + rb);
    float4 vm[4];
    const size_t mb = (size_t)node * (HEADS * DIMS) + lane * 4;
    #pragma unroll
    for (int h = 0; h < HEADS; h++) vm[h] = *(const float4*)(g_m + mb + h * DIMS);

    float dt[4][7];
    #pragma unroll
    for (int h = 0; h < 4; h++) {
        dt[h][0] = dot4(vm[h], vx);
        #pragma unroll
        for (int p = 0; p < 6; p++) dt[h][1 + p] = dot4(vm[h], av[p]);
    }
    #pragma unroll
    for (int h = 0; h < 4; h++)
        #pragma unroll
        for (int v = 0; v < 7; v++) {
            float t = dt[h][v];
            #pragma unroll
            for (int o = 16; o; o >>= 1) t += __shfl_xor_sync(0xffffffffu, t, o);
            dt[h][v] = t;
        }

    const int cnt0 = g_cnt[0][node], cnt1 = g_cnt[1][node];
    const float c0 = (float)cnt0, c1 = (float)cnt1;
    const float sc = 0.17677669529663687f;  // 1/sqrt(32)

    #pragma unroll
    for (int h = 0; h < 4; h++) {
        float s0 = dt[h][0] * sc;
        float mx = s0;
        float a0 = 0.f, b0 = 0.f, u0 = 0.f, n0 = 0.f;
        float a1 = 0.f, b1 = 0.f, u1 = 0.f, n1 = 0.f;
        if (cnt0) {
            a0 = dt[h][1] * sc; b0 = dt[h][2] * sc; u0 = dt[h][3] * sc; n0 = u0 / c0;
            mx = fmaxf(mx, fmaxf(fmaxf(a0, b0), fmaxf(u0, n0)));
        }
        if (cnt1) {
            a1 = dt[h][4] * sc; b1 = dt[h][5] * sc; u1 = dt[h][6] * sc; n1 = u1 / c1;
            mx = fmaxf(mx, fmaxf(fmaxf(a1, b1), fmaxf(u1, n1)));
        }
        float eself = __expf(s0 - mx);
        float den = eself;
        float wm0 = 0.f, wn0 = 0.f, ws0 = 0.f, wm1 = 0.f, wn1 = 0.f, ws1 = 0.f;
        if (cnt0) {
            float e1 = __expf(a0 - mx), e2 = __expf(b0 - mx);
            float e3 = __expf(u0 - mx), e4 = __expf(n0 - mx);
            den += e1 + e2 + e3 + e4;
            wm0 = e1; wn0 = e2; ws0 = e3 + e4 / c0;
        }
        if (cnt1) {
            float e1 = __expf(a1 - mx), e2 = __expf(b1 - mx);
            float e3 = __expf(u1 - mx), e4 = __expf(n1 - mx);
            den += e1 + e2 + e3 + e4;
            wm1 = e1; wn1 = e2; ws1 = e3 + e4 / c1;
        }
        float inv = 1.f / den;
        float4 z = make_float4(0.f, 0.f, 0.f, 0.f);
        axpy4(z, vx, eself * inv);
        if (cnt0) { axpy4(z, av[0], wm0 * inv); axpy4(z, av[1], wn0 * inv); axpy4(z, av[2], ws0 * inv); }
        if (cnt1) { axpy4(z, av[3], wm1 * inv); axpy4(z, av[4], wn1 * inv); axpy4(z, av[5], ws1 * inv); }

        __nv_bfloat16 h0 = __float2bfloat16(z.x), h1 = __float2bfloat16(z.y);
        __nv_bfloat16 h2 = __float2bfloat16(z.z), h3 = __float2bfloat16(z.w);
        __nv_bfloat16 l0 = __float2bfloat16(z.x - __bfloat162float(h0));
        __nv_bfloat16 l1 = __float2bfloat16(z.y - __bfloat162float(h1));
        __nv_bfloat16 l2 = __float2bfloat16(z.z - __bfloat162float(h2));
        __nv_bfloat16 l3 = __float2bfloat16(z.w - __bfloat162float(h3));
        *(uint2*)(g_zh + mb + h * DIMS) = make_uint2(pack_bf16(h0, h1), pack_bf16(h2, h3));
        *(uint2*)(g_zl + mb + h * DIMS) = make_uint2(pack_bf16(l0, l1), pack_bf16(l2, l3));
    }
}

// ---------------- GEMM2 (HMMA, cp.async-pipelined A+B): out = LN(z @ U^T + out_const) ----------------
__global__ __launch_bounds__(256) void gemm2_tc(const float* __restrict__ gamma,
                                                const float* __restrict__ beta,
                                                float* __restrict__ out) {
    extern __shared__ char sm[];
    const int tid = threadIdx.x, wid = tid >> 5, lane = tid & 31;
    const int warp_m = wid >> 2, warp_n = wid & 3;
    const int row0 = blockIdx.x * 128;
    const uint32_t sb = smem_to_u32(sm);
    const uint32_t lA = laneA_off(lane), lB = laneB_off(lane);

    auto issue = [&](int kc, int st) {
        uint32_t stb = sb + (uint32_t)st * 4 * TBYTES;
        for (int it = tid; it < 1024; it += 256) {
            int r = it >> 3, q = it & 7;
            int node = row0 + r;
            uint32_t dst = (uint32_t)(r * TSTRIDE + q * 8) * 2;
            size_t asrc = (size_t)node * 512 + kc * 64 + q * 8;
            uint32_t ok = (node < N_NODES) ? 16u : 0u;
            cp16(stb + dst, g_zh + asrc, ok);
            cp16(stb + TBYTES + dst, g_zl + asrc, ok);
            size_t bsrc = (size_t)r * 512 + kc * 64 + q * 8;
            cp16(stb + 2 * TBYTES + dst, g_Uh + bsrc, 16);
            cp16(stb + 3 * TBYTES + dst, g_Ul + bsrc, 16);
        }
        CP_COMMIT();
    };

    float acc[4][4][4];
    #pragma unroll
    for (int i = 0; i < 4; i++)
        #pragma unroll
        for (int j = 0; j < 4; j++)
            #pragma unroll
            for (int q = 0; q < 4; q++) acc[i][j][q] = 0.f;

    issue(0, 0);
    for (int kc = 0; kc < 8; kc++) {
        if (kc < 7) issue(kc + 1, (kc + 1) & 1);
        if (kc < 7) { CP_WAIT(1); } else { CP_WAIT(0); }
        __syncthreads();
        uint32_t stb = (uint32_t)(kc & 1) * 4 * TBYTES;
        mma_tile(sb, stb, stb + TBYTES, stb + 2 * TBYTES, stb + 3 * TBYTES,
                 lA, lB, warp_m, warp_n, acc);
        __syncthreads();
    }

    float* S = (float*)sm;                 // [128][133]
    float* stats = (float*)(sm + 128 * 133 * 4);
    #pragma unroll
    for (int mf = 0; mf < 4; mf++) {
        int r_lo = warp_m * 64 + mf * 16 + (lane >> 2);
        #pragma unroll
        for (int half = 0; half < 2; half++) {
            int r = r_lo + half * 8;
            #pragma unroll
            for (int nf = 0; nf < 4; nf++) {
                int col = warp_n * 32 + nf * 8 + (lane & 3) * 2;
                S[r * 133 + col]     = acc[mf][nf][half * 2 + 0] + g_oconst[col];
                S[r * 133 + col + 1] = acc[mf][nf][half * 2 + 1] + g_oconst[col + 1];
            }
        }
    }
    __syncthreads();
    if (tid < 128) {
        float s = 0.f, q = 0.f;
        #pragma unroll 8
        for (int j = 0; j < 128; j++) {
            float v = S[tid * 133 + j];
            s += v; q += v * v;
        }
        float mu = s * (1.f / 128.f);
        float var = q * (1.f / 128.f) - mu * mu;
        stats[tid] = mu;
        stats[128 + tid] = rsqrtf(var + 1e-5f);
    }
    __syncthreads();
    for (int it = tid; it < 128 * 32; it += 256) {
        int r = it >> 5, j = (it & 31) * 4;
        int node = row0 + r;
        if (node >= N_NODES) continue;
        float mu = stats[r], rs = stats[128 + r];
        float4 o;
        o.x = (S[r * 133 + j + 0] - mu) * rs * __ldg(gamma + j + 0) + __ldg(beta + j + 0);
        o.y = (S[r * 133 + j + 1] - mu) * rs * __ldg(gamma + j + 1) + __ldg(beta + j + 1);
        o.z = (S[r * 133 + j + 2] - mu) * rs * __ldg(gamma + j + 2) + __ldg(beta + j + 2);
        o.w = (S[r * 133 + j + 3] - mu) * rs * __ldg(gamma + j + 3) + __ldg(beta + j + 3);
        *(float4*)(out + (size_t)node * 128 + j) = o;
    }
}

// ---------------- launcher (graph-capturable 3-way fork/join, persistent streams) ----------------
extern "C" void kernel_launch(void* const* d_in, const int* in_sizes, int n_in,
                              void* d_out, int out_size) {
    const float* x     = (const float*)d_in[0];
    const int*   ei0   = (const int*)d_in[1];
    const int*   ei1   = (const int*)d_in[2];
    const float* w_in  = (const float*)d_in[3];
    const float* b_in  = (const float*)d_in[4];
    const float* w_out = (const float*)d_in[5];
    const float* b_out = (const float*)d_in[6];
    const float* gamma = (const float*)d_in[7];
    const float* beta  = (const float*)d_in[8];
    float* out = (float*)d_out;

    static bool inited = false;
    static cudaStream_t s1, s2;
    static cudaEvent_t evFork, evJ1, evJ2;
    if (!inited) {
        cudaStreamCreateWithFlags(&s1, cudaStreamNonBlocking);
        cudaStreamCreateWithFlags(&s2, cudaStreamNonBlocking);
        cudaEventCreateWithFlags(&evFork, cudaEventDisableTiming);
        cudaEventCreateWithFlags(&evJ1, cudaEventDisableTiming);
        cudaEventCreateWithFlags(&evJ2, cudaEventDisableTiming);
        cudaFuncSetAttribute(gemm1_tc, cudaFuncAttributeMaxDynamicSharedMemorySize, GEMM_SMEM);
        cudaFuncSetAttribute(gemm2_tc, cudaFuncAttributeMaxDynamicSharedMemorySize, GEMM_SMEM);
        inited = true;
    }

    cudaEventRecord(evFork, 0);
    cudaStreamWaitEvent(s1, evFork, 0);
    cudaStreamWaitEvent(s2, evFork, 0);

    // branch A: edge set 0
    zero_kernel<<<(N_NODES + 255) / 256, 256, 0, s1>>>(0);
    hist_kernel<<<(N_EDGES + 255) / 256, 256, 0, s1>>>(ei0, 0);
    scanA_kernel<<<NBLK, 1024, 0, s1>>>(0);
    scanC_kernel<<<NBLK, 1024, 0, s1>>>(0);
    fill_kernel<<<(N_EDGES + 255) / 256, 256, 0, s1>>>(ei0, 0);
    agg_kernel<<<(N_NODES + 7) / 8, 256, 0, s1>>>(x, 0);
    cudaEventRecord(evJ1, s1);

    // branch B: edge set 1
    zero_kernel<<<(N_NODES + 255) / 256, 256, 0, s2>>>(1);
    hist_kernel<<<(N_EDGES + 255) / 256, 256, 0, s2>>>(ei1, 1);
    scanA_kernel<<<NBLK, 1024, 0, s2>>>(1);
    scanC_kernel<<<NBLK, 1024, 0, s2>>>(1);
    fill_kernel<<<(N_EDGES + 255) / 256, 256, 0, s2>>>(ei1, 1);
    agg_kernel<<<(N_NODES + 7) / 8, 256, 0, s2>>>(x, 1);
    cudaEventRecord(evJ2, s2);

    // branch C (main): weight folding + GEMM1
    precompute_kernel<<<(2 * 512 * 128 + 512 + 128 + 255) / 256, 256>>>(w_in, b_in, w_out, b_out);
    const int GB = (N_NODES + 127) / 128;  // 391
    gemm1_tc<<<GB, 256, GEMM_SMEM>>>(x);

    // join
    cudaStreamWaitEvent(0, evJ1, 0);
    cudaStreamWaitEvent(0, evJ2, 0);
    attn_kernel<<<(N_NODES + 7) / 8, 256>>>(x);
    gemm2_tc<<<GB, 256, GEMM_SMEM>>>(gamma, beta, out);
}

// round 17
// speedup vs baseline: 1.0877x; 1.0187x over previous
#include <cuda_runtime.h>
#include <cuda_bf16.h>
#include <cstdint>

#define N_NODES 50000
#define N_EDGES 800000
#define DIMS 128
#define HEADS 4
#define NBLK 49   // ceil(50000/1024)

// ---------------- scratch (__device__ globals: allocation-free) ----------------
// g_cnt starts zeroed (static init); scanC re-zeros it after use, so every
// graph replay sees zeroed counts without a dedicated zero_kernel launch.
__device__ int   g_cnt[2][N_NODES];
__device__ int   g_cur[2][N_NODES];     // absolute write cursors (seeded by scanC)
__device__ int   g_off[2][N_NODES + 1];
__device__ int   g_adj[2][N_EDGES];
__device__ int   g_bsum[2][64];
__device__ float g_aggr[6ull * N_NODES * DIMS];            // planes: max0,min0,sum0,max1,min1,sum1
__device__ float g_m[(size_t)N_NODES * HEADS * DIMS];      // [node][h*128+j]
__device__ __nv_bfloat16 g_zh[(size_t)N_NODES * HEADS * DIMS];
__device__ __nv_bfloat16 g_zl[(size_t)N_NODES * HEADS * DIMS];
// folded weights (bf16 hi/lo split)
__device__ __nv_bfloat16 g_Bwh[512 * 128];  // [n][k]
__device__ __nv_bfloat16 g_Bwl[512 * 128];
__device__ __nv_bfloat16 g_Uh[128 * 512];   // [c][kk]
__device__ __nv_bfloat16 g_Ul[128 * 512];
__device__ float g_mconst[512];
__device__ float g_oconst[128];

// ---------------- warp MMA + async helpers (plain PTX, sm_80+) ----------------
__device__ __forceinline__ uint32_t smem_to_u32(const void* p) {
    uint32_t a;
    asm("{ .reg .u64 t; cvta.to.shared.u64 t, %1; cvt.u32.u64 %0, t; }" : "=r"(a) : "l"(p));
    return a;
}
__device__ __forceinline__ void ldsm4(uint32_t (&r)[4], uint32_t addr) {
    asm volatile("ldmatrix.sync.aligned.m8n8.x4.shared.b16 {%0,%1,%2,%3}, [%4];"
                 : "=r"(r[0]), "=r"(r[1]), "=r"(r[2]), "=r"(r[3]) : "r"(addr));
}
__device__ __forceinline__ void mma16816(float (&c)[4], const uint32_t (&a)[4],
                                         uint32_t b0, uint32_t b1) {
    asm volatile("mma.sync.aligned.m16n8k16.row.col.f32.bf16.bf16.f32 "
                 "{%0,%1,%2,%3}, {%4,%5,%6,%7}, {%8,%9}, {%0,%1,%2,%3};"
                 : "+f"(c[0]), "+f"(c[1]), "+f"(c[2]), "+f"(c[3])
                 : "r"(a[0]), "r"(a[1]), "r"(a[2]), "r"(a[3]), "r"(b0), "r"(b1));
}
__device__ __forceinline__ uint32_t pack_bf16(__nv_bfloat16 a, __nv_bfloat16 b) {
    __nv_bfloat162 t = __halves2bfloat162(a, b);
    return *(uint32_t*)&t;
}
__device__ __forceinline__ void cp16(uint32_t smem_addr, const void* gptr, uint32_t srcsize) {
    asm volatile("cp.async.cg.shared.global [%0], [%1], 16, %2;"
                 :: "r"(smem_addr), "l"(gptr), "r"(srcsize) : "memory");
}
#define CP_COMMIT() asm volatile("cp.async.commit_group;" ::: "memory")
#define CP_WAIT(n)  asm volatile("cp.async.wait_group %0;" :: "n"(n) : "memory")

// SMEM tile geometry: [128 rows][64 k] bf16, row stride 72 (144B, ldmatrix conflict-free)
#define TSTRIDE 72
#define TBYTES  (128 * TSTRIDE * 2)   // 18432
#define GEMM_SMEM (8 * TBYTES)        // 147456

// ---------------- CSR build (per edge set) ----------------
__global__ void hist_kernel(const int* __restrict__ ei, int set) {
    int e = blockIdx.x * blockDim.x + threadIdx.x;
    if (e >= N_EDGES) return;
    atomicAdd(&g_cnt[set][ei[N_EDGES + e]], 1);
}
// phase A: per-block sums
__global__ void scanA_kernel(int set) {
    __shared__ int sw[32];
    const int tid = threadIdx.x, lane = tid & 31, wid = tid >> 5;
    int i = blockIdx.x * 1024 + tid;
    int v = (i < N_NODES) ? g_cnt[set][i] : 0;
    #pragma unroll
    for (int o = 16; o; o >>= 1) v += __shfl_xor_sync(0xffffffffu, v, o);
    if (lane == 0) sw[wid] = v;
    __syncthreads();
    if (wid == 0) {
        int t = sw[lane];
        #pragma unroll
        for (int o = 16; o; o >>= 1) t += __shfl_xor_sync(0xffffffffu, t, o);
        if (lane == 0) g_bsum[set][blockIdx.x] = t;
    }
}
// phase C: per-block scan; block prefix inline; seeds g_cur = off; RESETS g_cnt
__global__ void scanC_kernel(int set) {
    __shared__ int sw[32];
    __shared__ int blockPre;
    const int tid = threadIdx.x, lane = tid & 31, wid = tid >> 5;
    if (wid == 0) {
        int j0 = lane, j1 = lane + 32;
        int v = 0;
        if (j0 < blockIdx.x && j0 < NBLK) v += g_bsum[set][j0];
        if (j1 < blockIdx.x && j1 < NBLK) v += g_bsum[set][j1];
        #pragma unroll
        for (int o = 16; o; o >>= 1) v += __shfl_xor_sync(0xffffffffu, v, o);
        if (lane == 0) blockPre = v;
    }
    int i = blockIdx.x * 1024 + tid;
    int v = (i < N_NODES) ? g_cnt[set][i] : 0;
    int incl = v;
    #pragma unroll
    for (int o = 1; o < 32; o <<= 1) {
        int t = __shfl_up_sync(0xffffffffu, incl, o);
        if (lane >= o) incl += t;
    }
    if (lane == 31) sw[wid] = incl;
    __syncthreads();
    if (wid == 0) {
        int t = sw[lane];
        #pragma unroll
        for (int o = 1; o < 32; o <<= 1) {
            int u = __shfl_up_sync(0xffffffffu, t, o);
            if (lane >= o) t += u;
        }
        sw[lane] = t;
    }
    __syncthreads();
    int add = (wid > 0) ? sw[wid - 1] : 0;
    if (i < N_NODES) {
        int off_end = blockPre + add + incl;
        g_off[set][i + 1] = off_end;
        g_cur[set][i] = off_end - v;   // exclusive prefix = write cursor
        g_cnt[set][i] = 0;             // self-clean for next replay
    }
    if (i == 0) g_off[set][0] = 0;
}
__global__ void fill_kernel(const int* __restrict__ ei, int set) {
    int e = blockIdx.x * blockDim.x + threadIdx.x;
    if (e >= N_EDGES) return;
    int s = ei[e], d = ei[N_EDGES + e];
    int p = atomicAdd(&g_cur[set][d], 1);
    g_adj[set][p] = s;
}

// ---------------- warp-per-node gather + max/min/sum (per set, 4-wide MLP) ----------------
__device__ __forceinline__ void acc3(float4& vmax, float4& vmin, float4& vsum, const float4 v) {
    vmax.x = fmaxf(vmax.x, v.x); vmax.y = fmaxf(vmax.y, v.y);
    vmax.z = fmaxf(vmax.z, v.z); vmax.w = fmaxf(vmax.w, v.w);
    vmin.x = fminf(vmin.x, v.x); vmin.y = fminf(vmin.y, v.y);
    vmin.z = fminf(vmin.z, v.z); vmin.w = fminf(vmin.w, v.w);
    vsum.x += v.x; vsum.y += v.y; vsum.z += v.z; vsum.w += v.w;
}
__global__ void agg_kernel(const float* __restrict__ x, int set) {
    int gw = (blockIdx.x * blockDim.x + threadIdx.x) >> 5;
    if (gw >= N_NODES) return;
    const int lane = threadIdx.x & 31;
    const int node = gw;
    const int beg = g_off[set][node], end = g_off[set][node + 1];
    const int* __restrict__ adj = g_adj[set];
    const size_t lo = (size_t)lane * 4;

    float4 vmax = make_float4(-3.402823466e38f, -3.402823466e38f, -3.402823466e38f, -3.402823466e38f);
    float4 vmin = make_float4( 3.402823466e38f,  3.402823466e38f,  3.402823466e38f,  3.402823466e38f);
    float4 vsum = make_float4(0.f, 0.f, 0.f, 0.f);

    int i = beg;
    for (; i + 4 <= end; i += 4) {
        int s0 = __ldg(adj + i + 0), s1 = __ldg(adj + i + 1);
        int s2 = __ldg(adj + i + 2), s3 = __ldg(adj + i + 3);
        float4 v0 = *(const float4*)(x + (size_t)s0 * DIMS + lo);
        float4 v1 = *(const float4*)(x + (size_t)s1 * DIMS + lo);
        float4 v2 = *(const float4*)(x + (size_t)s2 * DIMS + lo);
        float4 v3 = *(const float4*)(x + (size_t)s3 * DIMS + lo);
        acc3(vmax, vmin, vsum, v0);
        acc3(vmax, vmin, vsum, v1);
        acc3(vmax, vmin, vsum, v2);
        acc3(vmax, vmin, vsum, v3);
    }
    for (; i < end; i++) {
        int s = __ldg(adj + i);
        float4 v = *(const float4*)(x + (size_t)s * DIMS + lo);
        acc3(vmax, vmin, vsum, v);
    }

    const size_t plane = (size_t)N_NODES * DIMS;
    size_t base = ((size_t)(set * 3) * N_NODES + node) * DIMS + lo;
    if (end > beg) {
        *(float4*)(g_aggr + base)             = vmax;
        *(float4*)(g_aggr + base + plane)     = vmin;
        *(float4*)(g_aggr + base + 2 * plane) = vsum;
    } else {
        float4 z = make_float4(0.f, 0.f, 0.f, 0.f);
        *(float4*)(g_aggr + base)             = z;
        *(float4*)(g_aggr + base + plane)     = z;
        *(float4*)(g_aggr + base + 2 * plane) = z;
    }
}

// ---------------- fold weights: Bw, U, m_const, out_const ----------------
__global__ void precompute_kernel(const float* __restrict__ w_in,
                                  const float* __restrict__ b_in,
                                  const float* __restrict__ w_out,
                                  const float* __restrict__ b_out) {
    int t = blockIdx.x * blockDim.x + threadIdx.x;
    if (t < 512 * 128) {                    // Bw[n][k]
        int n = t >> 7, k = t & 127;
        int h = n >> 7, j = n & 127;
        float s = 0.f;
        #pragma unroll 8
        for (int i = 0; i < 32; i++)
            s += w_in[(size_t)(h * 32 + i) * 128 + k] * w_in[(size_t)(128 + h * 32 + i) * 128 + j];
        __nv_bfloat16 hi = __float2bfloat16(s);
        g_Bwh[t] = hi;
        g_Bwl[t] = __float2bfloat16(s - __bfloat162float(hi));
    } else if (t < 2 * 512 * 128) {         // U[c][kk]
        int u = t - 512 * 128;
        int c = u >> 9, kk = u & 511;
        int h = kk >> 7, d = kk & 127;
        float s = 0.f;
        #pragma unroll 8
        for (int i = 0; i < 32; i++)
            s += w_out[(size_t)c * 128 + h * 32 + i] * w_in[(size_t)(256 + h * 32 + i) * 128 + d];
        __nv_bfloat16 hi = __float2bfloat16(s);
        g_Uh[u] = hi;
        g_Ul[u] = __float2bfloat16(s - __bfloat162float(hi));
    } else if (t < 2 * 512 * 128 + 512) {   // m_const
        int n = t - 2 * 512 * 128;
        int h = n >> 7, j = n & 127;
        float s = 0.f;
        for (int i = 0; i < 32; i++)
            s += b_in[h * 32 + i] * w_in[(size_t)(128 + h * 32 + i) * 128 + j];
        g_mconst[n] = s;
    } else if (t < 2 * 512 * 128 + 512 + 128) {  // out_const
        int c = t - 2 * 512 * 128 - 512;
        float s = b_out[c];
        for (int n = 0; n < 128; n++)
            s += w_out[(size_t)c * 128 + n] * b_in[256 + n];
        g_oconst[c] = s;
    }
}

// per-lane ldmatrix source offsets (bytes) within a [*, TSTRIDE] bf16 tile
__device__ __forceinline__ uint32_t laneA_off(int lane) {
    int row = (lane < 16) ? lane : (lane - 16);
    int col = (lane < 16) ? 0 : 8;
    return (uint32_t)(row * TSTRIDE + col) * 2;
}
__device__ __forceinline__ uint32_t laneB_off(int lane) {
    int g = lane >> 3, r = lane & 7;
    int row = (g == 0 || g == 1) ? r : (8 + r);
    int col = (g == 1 || g == 3) ? 8 : 0;
    return (uint32_t)(row * TSTRIDE + col) * 2;
}
__device__ __forceinline__ void store_split4(char* base_h, char* base_l, int r, int k4, float4 v) {
    __nv_bfloat16 h0 = __float2bfloat16(v.x), h1 = __float2bfloat16(v.y);
    __nv_bfloat16 h2 = __float2bfloat16(v.z), h3 = __float2bfloat16(v.w);
    __nv_bfloat16 l0 = __float2bfloat16(v.x - __bfloat162float(h0));
    __nv_bfloat16 l1 = __float2bfloat16(v.y - __bfloat162float(h1));
    __nv_bfloat16 l2 = __float2bfloat16(v.z - __bfloat162float(h2));
    __nv_bfloat16 l3 = __float2bfloat16(v.w - __bfloat162float(h3));
    uint2 ph = make_uint2(pack_bf16(h0, h1), pack_bf16(h2, h3));
    uint2 pl = make_uint2(pack_bf16(l0, l1), pack_bf16(l2, l3));
    uint32_t off = (uint32_t)(r * TSTRIDE + k4 * 4) * 2;
    *(uint2*)(base_h + off) = ph;
    *(uint2*)(base_l + off) = pl;
}

// warp-tile MMA on one (A,B) smem tile pair with 3-pass hi/lo
__device__ __forceinline__ void mma_tile(uint32_t sb, uint32_t offAH, uint32_t offAL,
                                         uint32_t offBH, uint32_t offBL,
                                         uint32_t lA, uint32_t lB,
                                         int warp_m, int warp_n, float (&acc)[4][4][4]) {
    #pragma unroll
    for (int pass = 0; pass < 3; pass++) {
        const uint32_t Abase = sb + ((pass == 2) ? offAL : offAH);
        const uint32_t Bbase = sb + ((pass == 1) ? offBL : offBH);
        #pragma unroll
        for (int ks = 0; ks < 4; ks++) {
            uint32_t a[4][4];
            #pragma unroll
            for (int mf = 0; mf < 4; mf++)
                ldsm4(a[mf], Abase + lA + (uint32_t)((warp_m * 64 + mf * 16) * TSTRIDE + ks * 16) * 2);
            uint32_t b[2][4];
            #pragma unroll
            for (int nf2 = 0; nf2 < 2; nf2++)
                ldsm4(b[nf2], Bbase + lB + (uint32_t)((warp_n * 32 + nf2 * 16) * TSTRIDE + ks * 16) * 2);
            #pragma unroll
            for (int mf = 0; mf < 4; mf++)
                #pragma unroll
                for (int nf = 0; nf < 4; nf++)
                    mma16816(acc[mf][nf], a[mf], b[nf >> 1][(nf & 1) * 2], b[nf >> 1][(nf & 1) * 2 + 1]);
        }
    }
}

// ---------------- GEMM1 (HMMA, cp.async-pipelined B): m = x @ Bw^T + m_const ----------------
__global__ __launch_bounds__(256) void gemm1_tc(const float* __restrict__ x) {
    extern __shared__ char sm[];
    const int tid = threadIdx.x, wid = tid >> 5, lane = tid & 31;
    const int warp_m = wid >> 2, warp_n = wid & 3;
    const int row0 = blockIdx.x * 128;
    const uint32_t sb = smem_to_u32(sm);
    const uint32_t lA = laneA_off(lane), lB = laneB_off(lane);
    const uint32_t BBASE = 4 * TBYTES;

    for (int kc = 0; kc < 2; kc++) {
        char* ah = sm + (2 * kc) * TBYTES;
        char* al = sm + (2 * kc + 1) * TBYTES;
        for (int it = tid; it < 128 * 16; it += 256) {
            int r = it >> 4, q = it & 15;
            int node = row0 + r;
            float4 v = (node < N_NODES)
                ? *(const float4*)(x + (size_t)node * 128 + kc * 64 + q * 4)
                : make_float4(0.f, 0.f, 0.f, 0.f);
            store_split4(ah, al, r, q, v);
        }
    }

    auto issueB = [&](int s, int st) {
        int nc = s >> 1, kc = s & 1;
        uint32_t stb = sb + BBASE + (uint32_t)st * 2 * TBYTES;
        for (int it = tid; it < 1024; it += 256) {
            int r = it >> 3, q = it & 7;
            size_t src = (size_t)(nc * 128 + r) * 128 + kc * 64 + q * 8;
            uint32_t dst = (uint32_t)(r * TSTRIDE + q * 8) * 2;
            cp16(stb + dst, g_Bwh + src, 16);
            cp16(stb + TBYTES + dst, g_Bwl + src, 16);
        }
        CP_COMMIT();
    };

    issueB(0, 0);

    float acc[4][4][4];
    for (int s = 0; s < 8; s++) {
        int nc = s >> 1, kc = s & 1;
        if (kc == 0) {
            #pragma unroll
            for (int i = 0; i < 4; i++)
                #pragma unroll
                for (int j = 0; j < 4; j++)
                    #pragma unroll
                    for (int q = 0; q < 4; q++) acc[i][j][q] = 0.f;
        }
        if (s < 7) issueB(s + 1, (s + 1) & 1);
        if (s < 7) { CP_WAIT(1); } else { CP_WAIT(0); }
        __syncthreads();

        uint32_t offAH = (uint32_t)(2 * kc) * TBYTES;
        uint32_t offAL = offAH + TBYTES;
        uint32_t offBH = BBASE + (uint32_t)(s & 1) * 2 * TBYTES;
        uint32_t offBL = offBH + TBYTES;
        mma_tile(sb, offAH, offAL, offBH, offBL, lA, lB, warp_m, warp_n, acc);
        __syncthreads();

        if (kc == 1) {
            #pragma unroll
            for (int mf = 0; mf < 4; mf++) {
                int r_lo = row0 + warp_m * 64 + mf * 16 + (lane >> 2);
                #pragma unroll
                for (int half = 0; half < 2; half++) {
                    int node = r_lo + half * 8;
                    if (node >= N_NODES) continue;
                    #pragma unroll
                    for (int nf = 0; nf < 4; nf++) {
                        int col = nc * 128 + warp_n * 32 + nf * 8 + (lane & 3) * 2;
                        float2 o;
                        o.x = acc[mf][nf][half * 2 + 0] + g_mconst[col];
                        o.y = acc[mf][nf][half * 2 + 1] + g_mconst[col + 1];
                        *(float2*)(g_m + (size_t)node * 512 + col) = o;
                    }
                }
            }
        }
    }
}

// ---------------- scores + softmax + z (warp per node; z written as bf16 hi/lo) ----------------
__device__ __forceinline__ float dot4(const float4 a, const float4 b) {
    return a.x * b.x + a.y * b.y + a.z * b.z + a.w * b.w;
}
__device__ __forceinline__ void axpy4(float4& z, const float4 v, float s) {
    z.x += v.x * s; z.y += v.y * s; z.z += v.z * s; z.w += v.w * s;
}
__global__ void attn_kernel(const float* __restrict__ x) {
    int gw = (blockIdx.x * blockDim.x + threadIdx.x) >> 5;
    if (gw >= N_NODES) return;
    const int lane = threadIdx.x & 31;
    const int node = gw;
    const size_t rb = (size_t)node * DIMS + lane * 4;
    const size_t plane = (size_t)N_NODES * DIMS;

    float4 vx = *(const float4*)(x + rb);
    float4 av[6];
    #pragma unroll
    for (int p = 0; p < 6; p++) av[p] = *(const float4*)(g_aggr + p * plane + rb);
    float4 vm[4];
    const size_t mb = (size_t)node * (HEADS * DIMS) + lane * 4;
    #pragma unroll
    for (int h = 0; h < HEADS; h++) vm[h] = *(const float4*)(g_m + mb + h * DIMS);

    float dt[4][7];
    #pragma unroll
    for (int h = 0; h < 4; h++) {
        dt[h][0] = dot4(vm[h], vx);
        #pragma unroll
        for (int p = 0; p < 6; p++) dt[h][1 + p] = dot4(vm[h], av[p]);
    }
    #pragma unroll
    for (int h = 0; h < 4; h++)
        #pragma unroll
        for (int v = 0; v < 7; v++) {
            float t = dt[h][v];
            #pragma unroll
            for (int o = 16; o; o >>= 1) t += __shfl_xor_sync(0xffffffffu, t, o);
            dt[h][v] = t;
        }

    // counts from offsets (g_cnt is reset by scanC for replay hygiene)
    const int cnt0 = g_off[0][node + 1] - g_off[0][node];
    const int cnt1 = g_off[1][node + 1] - g_off[1][node];
    const float c0 = (float)cnt0, c1 = (float)cnt1;
    const float sc = 0.17677669529663687f;  // 1/sqrt(32)

    #pragma unroll
    for (int h = 0; h < 4; h++) {
        float s0 = dt[h][0] * sc;
        float mx = s0;
        float a0 = 0.f, b0 = 0.f, u0 = 0.f, n0 = 0.f;
        float a1 = 0.f, b1 = 0.f, u1 = 0.f, n1 = 0.f;
        if (cnt0) {
            a0 = dt[h][1] * sc; b0 = dt[h][2] * sc; u0 = dt[h][3] * sc; n0 = u0 / c0;
            mx = fmaxf(mx, fmaxf(fmaxf(a0, b0), fmaxf(u0, n0)));
        }
        if (cnt1) {
            a1 = dt[h][4] * sc; b1 = dt[h][5] * sc; u1 = dt[h][6] * sc; n1 = u1 / c1;
            mx = fmaxf(mx, fmaxf(fmaxf(a1, b1), fmaxf(u1, n1)));
        }
        float eself = __expf(s0 - mx);
        float den = eself;
        float wm0 = 0.f, wn0 = 0.f, ws0 = 0.f, wm1 = 0.f, wn1 = 0.f, ws1 = 0.f;
        if (cnt0) {
            float e1 = __expf(a0 - mx), e2 = __expf(b0 - mx);
            float e3 = __expf(u0 - mx), e4 = __expf(n0 - mx);
            den += e1 + e2 + e3 + e4;
            wm0 = e1; wn0 = e2; ws0 = e3 + e4 / c0;
        }
        if (cnt1) {
            float e1 = __expf(a1 - mx), e2 = __expf(b1 - mx);
            float e3 = __expf(u1 - mx), e4 = __expf(n1 - mx);
            den += e1 + e2 + e3 + e4;
            wm1 = e1; wn1 = e2; ws1 = e3 + e4 / c1;
        }
        float inv = 1.f / den;
        float4 z = make_float4(0.f, 0.f, 0.f, 0.f);
        axpy4(z, vx, eself * inv);
        if (cnt0) { axpy4(z, av[0], wm0 * inv); axpy4(z, av[1], wn0 * inv); axpy4(z, av[2], ws0 * inv); }
        if (cnt1) { axpy4(z, av[3], wm1 * inv); axpy4(z, av[4], wn1 * inv); axpy4(z, av[5], ws1 * inv); }

        __nv_bfloat16 h0 = __float2bfloat16(z.x), h1 = __float2bfloat16(z.y);
        __nv_bfloat16 h2 = __float2bfloat16(z.z), h3 = __float2bfloat16(z.w);
        __nv_bfloat16 l0 = __float2bfloat16(z.x - __bfloat162float(h0));
        __nv_bfloat16 l1 = __float2bfloat16(z.y - __bfloat162float(h1));
        __nv_bfloat16 l2 = __float2bfloat16(z.z - __bfloat162float(h2));
        __nv_bfloat16 l3 = __float2bfloat16(z.w - __bfloat162float(h3));
        *(uint2*)(g_zh + mb + h * DIMS) = make_uint2(pack_bf16(h0, h1), pack_bf16(h2, h3));
        *(uint2*)(g_zl + mb + h * DIMS) = make_uint2(pack_bf16(l0, l1), pack_bf16(l2, l3));
    }
}

// ---------------- GEMM2 (HMMA, cp.async-pipelined A+B): out = LN(z @ U^T + out_const) ----------------
__global__ __launch_bounds__(256) void gemm2_tc(const float* __restrict__ gamma,
                                                const float* __restrict__ beta,
                                                float* __restrict__ out) {
    extern __shared__ char sm[];
    const int tid = threadIdx.x, wid = tid >> 5, lane = tid & 31;
    const int warp_m = wid >> 2, warp_n = wid & 3;
    const int row0 = blockIdx.x * 128;
    const uint32_t sb = smem_to_u32(sm);
    const uint32_t lA = laneA_off(lane), lB = laneB_off(lane);

    auto issue = [&](int kc, int st) {
        uint32_t stb = sb + (uint32_t)st * 4 * TBYTES;
        for (int it = tid; it < 1024; it += 256) {
            int r = it >> 3, q = it & 7;
            int node = row0 + r;
            uint32_t dst = (uint32_t)(r * TSTRIDE + q * 8) * 2;
            size_t asrc = (size_t)node * 512 + kc * 64 + q * 8;
            uint32_t ok = (node < N_NODES) ? 16u : 0u;
            cp16(stb + dst, g_zh + asrc, ok);
            cp16(stb + TBYTES + dst, g_zl + asrc, ok);
            size_t bsrc = (size_t)r * 512 + kc * 64 + q * 8;
            cp16(stb + 2 * TBYTES + dst, g_Uh + bsrc, 16);
            cp16(stb + 3 * TBYTES + dst, g_Ul + bsrc, 16);
        }
        CP_COMMIT();
    };

    float acc[4][4][4];
    #pragma unroll
    for (int i = 0; i < 4; i++)
        #pragma unroll
        for (int j = 0; j < 4; j++)
            #pragma unroll
            for (int q = 0; q < 4; q++) acc[i][j][q] = 0.f;

    issue(0, 0);
    for (int kc = 0; kc < 8; kc++) {
        if (kc < 7) issue(kc + 1, (kc + 1) & 1);
        if (kc < 7) { CP_WAIT(1); } else { CP_WAIT(0); }
        __syncthreads();
        uint32_t stb = (uint32_t)(kc & 1) * 4 * TBYTES;
        mma_tile(sb, stb, stb + TBYTES, stb + 2 * TBYTES, stb + 3 * TBYTES,
                 lA, lB, warp_m, warp_n, acc);
        __syncthreads();
    }

    float* S = (float*)sm;                 // [128][133]
    float* stats = (float*)(sm + 128 * 133 * 4);
    #pragma unroll
    for (int mf = 0; mf < 4; mf++) {
        int r_lo = warp_m * 64 + mf * 16 + (lane >> 2);
        #pragma unroll
        for (int half = 0; half < 2; half++) {
            int r = r_lo + half * 8;
            #pragma unroll
            for (int nf = 0; nf < 4; nf++) {
                int col = warp_n * 32 + nf * 8 + (lane & 3) * 2;
                S[r * 133 + col]     = acc[mf][nf][half * 2 + 0] + g_oconst[col];
                S[r * 133 + col + 1] = acc[mf][nf][half * 2 + 1] + g_oconst[col + 1];
            }
        }
    }
    __syncthreads();
    if (tid < 128) {
        float s = 0.f, q = 0.f;
        #pragma unroll 8
        for (int j = 0; j < 128; j++) {
            float v = S[tid * 133 + j];
            s += v; q += v * v;
        }
        float mu = s * (1.f / 128.f);
        float var = q * (1.f / 128.f) - mu * mu;
        stats[tid] = mu;
        stats[128 + tid] = rsqrtf(var + 1e-5f);
    }
    __syncthreads();
    for (int it = tid; it < 128 * 32; it += 256) {
        int r = it >> 5, j = (it & 31) * 4;
        int node = row0 + r;
        if (node >= N_NODES) continue;
        float mu = stats[r], rs = stats[128 + r];
        float4 o;
        o.x = (S[r * 133 + j + 0] - mu) * rs * __ldg(gamma + j + 0) + __ldg(beta + j + 0);
        o.y = (S[r * 133 + j + 1] - mu) * rs * __ldg(gamma + j + 1) + __ldg(beta + j + 1);
        o.z = (S[r * 133 + j + 2] - mu) * rs * __ldg(gamma + j + 2) + __ldg(beta + j + 2);
        o.w = (S[r * 133 + j + 3] - mu) * rs * __ldg(gamma + j + 3) + __ldg(beta + j + 3);
        *(float4*)(out + (size_t)node * 128 + j) = o;
    }
}

// ---------------- launcher (graph-capturable 3-way fork/join, persistent streams) ----------------
extern "C" void kernel_launch(void* const* d_in, const int* in_sizes, int n_in,
                              void* d_out, int out_size) {
    const float* x     = (const float*)d_in[0];
    const int*   ei0   = (const int*)d_in[1];
    const int*   ei1   = (const int*)d_in[2];
    const float* w_in  = (const float*)d_in[3];
    const float* b_in  = (const float*)d_in[4];
    const float* w_out = (const float*)d_in[5];
    const float* b_out = (const float*)d_in[6];
    const float* gamma = (const float*)d_in[7];
    const float* beta  = (const float*)d_in[8];
    float* out = (float*)d_out;

    static bool inited = false;
    static cudaStream_t s1, s2;
    static cudaEvent_t evFork, evJ1, evJ2;
    if (!inited) {
        cudaStreamCreateWithFlags(&s1, cudaStreamNonBlocking);
        cudaStreamCreateWithFlags(&s2, cudaStreamNonBlocking);
        cudaEventCreateWithFlags(&evFork, cudaEventDisableTiming);
        cudaEventCreateWithFlags(&evJ1, cudaEventDisableTiming);
        cudaEventCreateWithFlags(&evJ2, cudaEventDisableTiming);
        cudaFuncSetAttribute(gemm1_tc, cudaFuncAttributeMaxDynamicSharedMemorySize, GEMM_SMEM);
        cudaFuncSetAttribute(gemm2_tc, cudaFuncAttributeMaxDynamicSharedMemorySize, GEMM_SMEM);
        inited = true;
    }

    cudaEventRecord(evFork, 0);
    cudaStreamWaitEvent(s1, evFork, 0);
    cudaStreamWaitEvent(s2, evFork, 0);

    // branch A: edge set 0 (g_cnt pre-zeroed: static init on first call, scanC reset thereafter)
    hist_kernel<<<(N_EDGES + 255) / 256, 256, 0, s1>>>(ei0, 0);
    scanA_kernel<<<NBLK, 1024, 0, s1>>>(0);
    scanC_kernel<<<NBLK, 1024, 0, s1>>>(0);
    fill_kernel<<<(N_EDGES + 255) / 256, 256, 0, s1>>>(ei0, 0);
    agg_kernel<<<(N_NODES + 7) / 8, 256, 0, s1>>>(x, 0);
    cudaEventRecord(evJ1, s1);

    // branch B: edge set 1
    hist_kernel<<<(N_EDGES + 255) / 256, 256, 0, s2>>>(ei1, 1);
    scanA_kernel<<<NBLK, 1024, 0, s2>>>(1);
    scanC_kernel<<<NBLK, 1024, 0, s2>>>(1);
    fill_kernel<<<(N_EDGES + 255) / 256, 256, 0, s2>>>(ei1, 1);
    agg_kernel<<<(N_NODES + 7) / 8, 256, 0, s2>>>(x, 1);
    cudaEventRecord(evJ2, s2);

    // branch C (main): weight folding + GEMM1
    precompute_kernel<<<(2 * 512 * 128 + 512 + 128 + 255) / 256, 256>>>(w_in, b_in, w_out, b_out);
    const int GB = (N_NODES + 127) / 128;  // 391
    gemm1_tc<<<GB, 256, GEMM_SMEM>>>(x);

    // join
    cudaStreamWaitEvent(0, evJ1, 0);
    cudaStreamWaitEvent(0, evJ2, 0);
    attn_kernel<<<(N_NODES + 7) / 8, 256>>>(x);
    gemm2_tc<<<GB, 256, GEMM_SMEM>>>(gamma, beta, out);
}